// round 6
// baseline (speedup 1.0000x reference)
#include <cuda_runtime.h>
#include <cuda_fp16.h>
#include <math.h>

#define NTOK 1280
#define DMOD 512
#define NH   16
#define DH   32
#define DFF  2048
#define NITER 20

// ---------------- scratch ----------------
__device__ __half g_logKh [NH*NTOK*NTOK];   // (h, n, m) fp16 — single copy, L2-resident
__device__ float g_hn  [NTOK*DMOD];
__device__ float g_qkvg[NTOK*4*DMOD];       // [q | k | v | gate]
__device__ float g_lu [NH*NTOK];
__device__ float g_lv [NH*NTOK];
__device__ float g_xc [NH*NTOK*3];
__device__ float g_rows[NH*NTOK];
__device__ float g_o  [NTOK*DMOD];
__device__ float g_h2 [NTOK*DMOD];
__device__ float g_hf [NTOK*DMOD];
__device__ float g_t12[NTOK*2*DFF];         // [t1 | t2]
__device__ float g_t1 [NTOK*DFF];
__device__ float g_part[4*NTOK*DMOD];       // split-K partials

__constant__ float c_eps[NH] = {0.5f,0.5f,0.5f,0.5f, 1.f,1.f,1.f,1.f,
                                2.f,2.f,2.f,2.f, 4.f,4.f,4.f,4.f};

struct Ptr4 { const float* p[4]; };

// ---------------- utility kernels ----------------
__global__ void zero_kernel(float* p, int n) {
    int i = blockIdx.x * blockDim.x + threadIdx.x;
    if (i < n) p[i] = 0.f;
}

__global__ void copy_uv_kernel(const float* __restrict__ lu, const float* __restrict__ lv,
                               float* __restrict__ o1, float* __restrict__ o2) {
    int i = blockIdx.x * blockDim.x + threadIdx.x;
    if (i < NH*NTOK) { o1[i] = lu[i]; o2[i] = lv[i]; }
}

__global__ void ln_kernel(const float* __restrict__ in, const float* __restrict__ g,
                          const float* __restrict__ b, float* __restrict__ out) {
    int row = blockIdx.x;
    int t = threadIdx.x;
    const float* x = in + (size_t)row * DMOD;
    float v0 = x[t], v1 = x[t + 256];
    __shared__ float red[256];
    red[t] = v0 + v1;
    __syncthreads();
    for (int o = 128; o > 0; o >>= 1) { if (t < o) red[t] += red[t + o]; __syncthreads(); }
    float mean = red[0] * (1.f / DMOD);
    __syncthreads();
    float d0 = v0 - mean, d1 = v1 - mean;
    red[t] = d0 * d0 + d1 * d1;
    __syncthreads();
    for (int o = 128; o > 0; o >>= 1) { if (t < o) red[t] += red[t + o]; __syncthreads(); }
    float r = rsqrtf(red[0] * (1.f / DMOD) + 1e-5f);
    out[(size_t)row * DMOD + t]       = d0 * r * g[t]       + b[t];
    out[(size_t)row * DMOD + t + 256] = d1 * r * g[t + 256] + b[t + 256];
}

// per-head QK layernorm; blockIdx.y selects Q (0) or K (1); row stride 4*DMOD
__global__ void qkln_kernel(float* __restrict__ base) {
    int gidx = blockIdx.x * 8 + (threadIdx.x >> 5);
    int lane = threadIdx.x & 31;
    if (gidx >= NTOK * NH) return;
    int n = gidx / NH, h = gidx % NH;
    float* p = base + (size_t)n * (4*DMOD) + blockIdx.y * DMOD + h * DH;
    float v = p[lane];
    float s = v;
    for (int o = 16; o; o >>= 1) s += __shfl_xor_sync(0xffffffffu, s, o);
    float mean = s * (1.f / 32.f);
    float d = v - mean;
    float s2 = d * d;
    for (int o = 16; o; o >>= 1) s2 += __shfl_xor_sync(0xffffffffu, s2, o);
    p[lane] = d * rsqrtf(s2 * (1.f / 32.f) + 1e-5f);
}

// ---------------- TF32 tensor-core GEMM ----------------
__device__ __forceinline__ unsigned f2tf32(float f) {
    unsigned u;
    asm("cvt.rna.tf32.f32 %0, %1;" : "=r"(u) : "f"(f));
    return u;
}

__device__ __forceinline__ void mma_tf32(float c[4], const unsigned a[4], const unsigned b[2]) {
    asm volatile("mma.sync.aligned.m16n8k8.row.col.f32.tf32.tf32.f32 "
        "{%0,%1,%2,%3}, {%4,%5,%6,%7}, {%8,%9}, {%0,%1,%2,%3};"
        : "+f"(c[0]), "+f"(c[1]), "+f"(c[2]), "+f"(c[3])
        : "r"(a[0]), "r"(a[1]), "r"(a[2]), "r"(a[3]), "r"(b[0]), "r"(b[1]));
}

// C[M=1280, Nn] = A[1280,K] @ Bsel[Nn,K]^T, output to C + blockIdx.z*1280*Nn.
__global__ void tc_gemm(const float* __restrict__ A, Ptr4 B4, float* __restrict__ C,
                        int Nn, int K, int colsPer, int KC) {
    __shared__ float As[32][136];
    __shared__ float Bs[32][72];
    int tid = threadIdx.x;
    int m0 = blockIdx.y * 128, n0 = blockIdx.x * 64;
    const float* B = B4.p[n0 / colsPer] + (size_t)(n0 % colsPer) * K;
    int kbeg = blockIdx.z * KC, kend = kbeg + KC;

    int arow = tid >> 1, akseg = (tid & 1) << 4;
    int brow = tid & 63, bkseg = (tid >> 6) << 3;
    const float* Ap = A + (size_t)(m0 + arow) * K + akseg;
    const float* Bp = B + (size_t)brow * K + bkseg;

    int lane = tid & 31, g = lane >> 2, t = lane & 3;
    int wm = tid >> 6;
    int wn = (tid >> 5) & 1;
    int mBase = wm * 32, nBase = wn * 32;

    float c[2][4][4];
#pragma unroll
    for (int mi = 0; mi < 2; mi++)
#pragma unroll
        for (int ni = 0; ni < 4; ni++)
#pragma unroll
            for (int r = 0; r < 4; r++) c[mi][ni][r] = 0.f;

    for (int k0 = kbeg; k0 < kend; k0 += 32) {
        __syncthreads();
#pragma unroll
        for (int i = 0; i < 4; i++) {
            float4 a4 = *(const float4*)(Ap + k0 + 4 * i);
            As[akseg + 4*i + 0][arow] = __uint_as_float(f2tf32(a4.x));
            As[akseg + 4*i + 1][arow] = __uint_as_float(f2tf32(a4.y));
            As[akseg + 4*i + 2][arow] = __uint_as_float(f2tf32(a4.z));
            As[akseg + 4*i + 3][arow] = __uint_as_float(f2tf32(a4.w));
        }
#pragma unroll
        for (int i = 0; i < 2; i++) {
            float4 b4 = *(const float4*)(Bp + k0 + 4 * i);
            Bs[bkseg + 4*i + 0][brow] = __uint_as_float(f2tf32(b4.x));
            Bs[bkseg + 4*i + 1][brow] = __uint_as_float(f2tf32(b4.y));
            Bs[bkseg + 4*i + 2][brow] = __uint_as_float(f2tf32(b4.z));
            Bs[bkseg + 4*i + 3][brow] = __uint_as_float(f2tf32(b4.w));
        }
        __syncthreads();
#pragma unroll
        for (int ks = 0; ks < 32; ks += 8) {
            unsigned a[2][4], b[4][2];
#pragma unroll
            for (int mi = 0; mi < 2; mi++) {
                int mo = mBase + mi * 16 + g;
                a[mi][0] = __float_as_uint(As[ks + t][mo]);
                a[mi][1] = __float_as_uint(As[ks + t][mo + 8]);
                a[mi][2] = __float_as_uint(As[ks + t + 4][mo]);
                a[mi][3] = __float_as_uint(As[ks + t + 4][mo + 8]);
            }
#pragma unroll
            for (int ni = 0; ni < 4; ni++) {
                int no = nBase + ni * 8 + g;
                b[ni][0] = __float_as_uint(Bs[ks + t][no]);
                b[ni][1] = __float_as_uint(Bs[ks + t + 4][no]);
            }
#pragma unroll
            for (int mi = 0; mi < 2; mi++)
#pragma unroll
                for (int ni = 0; ni < 4; ni++)
                    mma_tf32(c[mi][ni], a[mi], b[ni]);
        }
    }

    float* Co = C + (size_t)blockIdx.z * NTOK * Nn;
#pragma unroll
    for (int mi = 0; mi < 2; mi++) {
        int r0 = m0 + mBase + mi * 16 + g;
#pragma unroll
        for (int ni = 0; ni < 4; ni++) {
            int col = n0 + nBase + ni * 8 + 2 * t;
            *(float2*)(Co + (size_t)r0 * Nn + col)       = make_float2(c[mi][ni][0], c[mi][ni][1]);
            *(float2*)(Co + (size_t)(r0 + 8) * Nn + col) = make_float2(c[mi][ni][2], c[mi][ni][3]);
        }
    }
}

__global__ void reduce_add(const float* __restrict__ R, const float* __restrict__ part,
                           int Z, float* __restrict__ out, int n) {
    int i = blockIdx.x * 256 + threadIdx.x;
    if (i >= n) return;
    float a = R[i];
    for (int z = 0; z < Z; z++) a += part[(size_t)z * n + i];
    out[i] = a;
}

// ---------------- logK build: 64x64 tile, 4x4 register blocking, single copy ----------------
__global__ void build_logk(const float* __restrict__ wrel, const float* __restrict__ xres,
                           const float* __restrict__ wdist) {
    __shared__ float Qs[32][68];      // [k][n]
    __shared__ float Ks[32][68];      // [k][m]
    __shared__ float xa[64][3], xb[64][3];
    int h = blockIdx.z;
    int n0 = blockIdx.y * 64, m0 = blockIdx.x * 64;
    int t = threadIdx.x;

    {
        int r = t >> 2, seg = (t & 3) << 3;
        const float* qp = g_qkvg + (size_t)(n0 + r) * (4*DMOD) + h * DH + seg;
        const float* kp = g_qkvg + (size_t)(m0 + r) * (4*DMOD) + DMOD + h * DH + seg;
#pragma unroll
        for (int i = 0; i < 2; i++) {
            float4 q4 = *(const float4*)(qp + 4*i);
            float4 k4 = *(const float4*)(kp + 4*i);
            Qs[seg + 4*i + 0][r] = q4.x; Qs[seg + 4*i + 1][r] = q4.y;
            Qs[seg + 4*i + 2][r] = q4.z; Qs[seg + 4*i + 3][r] = q4.w;
            Ks[seg + 4*i + 0][r] = k4.x; Ks[seg + 4*i + 1][r] = k4.y;
            Ks[seg + 4*i + 2][r] = k4.z; Ks[seg + 4*i + 3][r] = k4.w;
        }
    }
    if (t < 192) { int r = t / 3, c = t % 3; xa[r][c] = xres[(n0 + r) * 3 + c]; }
    if (t >= 64 && t < 256) {
        int u = t - 64;
        if (u < 192) { int r = u / 3, c = u % 3; xb[r][c] = xres[(m0 + r) * 3 + c]; }
    }
    __syncthreads();

    int tm = t >> 4, tn = t & 15;
    float acc[4][4] = {};
#pragma unroll
    for (int k = 0; k < 32; k++) {
        float4 av = *(const float4*)&Qs[k][tm << 2];
        float4 bv = *(const float4*)&Ks[k][tn << 2];
        float a[4] = {av.x, av.y, av.z, av.w};
        float bb[4] = {bv.x, bv.y, bv.z, bv.w};
#pragma unroll
        for (int i = 0; i < 4; i++)
#pragma unroll
            for (int j = 0; j < 4; j++) acc[i][j] += a[i] * bb[j];
    }

    float inve = 1.f / c_eps[h];
    float wd = wdist[h] * 0.01f;
    const float scale = 0.17677669529663687f;
#pragma unroll
    for (int i = 0; i < 4; i++) {
        int nl = (tm << 2) + i;
        int n = n0 + nl;
        float ax0 = xa[nl][0], ax1 = xa[nl][1], ax2 = xa[nl][2];
        size_t base = ((size_t)h * NTOK + n) * NTOK + m0 + (tn << 2);
        float4 w4 = *(const float4*)(wrel + base);
        float v[4];
#pragma unroll
        for (int j = 0; j < 4; j++) {
            int ml = (tn << 2) + j;
            float dx = ax0 - xb[ml][0];
            float dy = ax1 - xb[ml][1];
            float dz = ax2 - xb[ml][2];
            float d2 = dx * dx + dy * dy + dz * dz;
            float wr = (j == 0) ? w4.x : (j == 1) ? w4.y : (j == 2) ? w4.z : w4.w;
            v[j] = (acc[i][j] * scale + wr - wd * d2) * inve;
        }
        __half2 h01 = __floats2half2_rn(v[0], v[1]);
        __half2 h23 = __floats2half2_rn(v[2], v[3]);
        *(__half2*)(g_logKh + base)     = h01;
        *(__half2*)(g_logKh + base + 2) = h23;
    }
}

// ---------------- Sinkhorn ----------------
__device__ __forceinline__ void lse_merge(float& m, float& s, float mo, float so) {
    float d = m - mo;
    float e = __expf(-fabsf(d));
    s = (d >= 0.f) ? (s + so * e) : (so + s * e);
    m = fmaxf(m, mo);
}

// row half-step: lu[h,n] = fi*(log(mu) - LSE_m(logK[h,n,m] + lv[h,m]))
__global__ void sinkhorn_row(const float* __restrict__ lv, const float* __restrict__ marg,
                             float* __restrict__ out) {
    int h = blockIdx.y;
    __shared__ float bs[NTOK];
    for (int i = threadIdx.x; i < NTOK; i += 256) bs[i] = lv[h * NTOK + i];
    __syncthreads();
    int warp = threadIdx.x >> 5, lane = threadIdx.x & 31;
    int row = blockIdx.x * 8 + warp;
    const uint4* pv = (const uint4*)(g_logKh + ((size_t)h * NTOK + row) * NTOK);
    float m = -1e30f, s = 0.f;
#pragma unroll
    for (int c = 0; c < 5; c++) {
        uint4 u = pv[c * 32 + lane];
        int jb = (c * 32 + lane) * 8;
        const __half2* hh = (const __half2*)&u;
        float2 f0 = __half22float2(hh[0]);
        float2 f1 = __half22float2(hh[1]);
        float2 f2 = __half22float2(hh[2]);
        float2 f3 = __half22float2(hh[3]);
        float x0 = f0.x + bs[jb + 0], x1 = f0.y + bs[jb + 1];
        float x2 = f1.x + bs[jb + 2], x3 = f1.y + bs[jb + 3];
        float x4 = f2.x + bs[jb + 4], x5 = f2.y + bs[jb + 5];
        float x6 = f3.x + bs[jb + 6], x7 = f3.y + bs[jb + 7];
        float ma = fmaxf(x0, x1), sa = 1.f + __expf(-fabsf(x0 - x1));
        float mb = fmaxf(x2, x3), sb = 1.f + __expf(-fabsf(x2 - x3));
        float mc = fmaxf(x4, x5), sc = 1.f + __expf(-fabsf(x4 - x5));
        float md = fmaxf(x6, x7), sd = 1.f + __expf(-fabsf(x6 - x7));
        lse_merge(ma, sa, mb, sb);
        lse_merge(mc, sc, md, sd);
        lse_merge(ma, sa, mc, sc);
        lse_merge(m, s, ma, sa);
    }
    for (int o = 16; o; o >>= 1) {
        float mo = __shfl_xor_sync(0xffffffffu, m, o);
        float so = __shfl_xor_sync(0xffffffffu, s, o);
        lse_merge(m, s, mo, so);
    }
    if (lane == 0) {
        float fi = 1.f / (1.f + c_eps[h]);
        out[h * NTOK + row] = fi * (logf(fmaxf(marg[h * NTOK + row], 1e-8f)) - (m + logf(s)));
    }
}

// col half-step: lv[h,m] = fi*(log(nu) - LSE_n(logK[h,n,m] + lu[h,n]))
// grid (NTOK/64, NH); 8 warps; warp w handles rows [w*160,(w+1)*160) of this block's 64 cols.
__global__ void sinkhorn_col(const float* __restrict__ lu, const float* __restrict__ marg,
                             float* __restrict__ out) {
    int h = blockIdx.y;
    int m0 = blockIdx.x * 64;
    __shared__ float bs[NTOK];
    __shared__ float sm[8][64], ss[8][64];
    for (int i = threadIdx.x; i < NTOK; i += 256) bs[i] = lu[h * NTOK + i];
    __syncthreads();
    int warp = threadIdx.x >> 5, lane = threadIdx.x & 31;
    int r0 = warp * 160;
    const __half2* p = (const __half2*)(g_logKh + ((size_t)h * NTOK + r0) * NTOK + m0) + lane;
    const int STRIDE2 = NTOK / 2;  // half2 elements per row
    float ma = -1e30f, sa = 0.f;   // col m0 + 2*lane
    float mb = -1e30f, sb = 0.f;   // col m0 + 2*lane + 1
#pragma unroll 4
    for (int r = 0; r < 160; r++) {
        float2 f = __half22float2(p[(size_t)r * STRIDE2]);
        float b = bs[r0 + r];
        float xa = f.x + b, xb = f.y + b;
        lse_merge(ma, sa, xa, 1.f);
        lse_merge(mb, sb, xb, 1.f);
    }
    sm[warp][2*lane]   = ma; ss[warp][2*lane]   = sa;
    sm[warp][2*lane+1] = mb; ss[warp][2*lane+1] = sb;
    __syncthreads();
    if (threadIdx.x < 64) {
        int c = threadIdx.x;
        float m = sm[0][c], s = ss[0][c];
#pragma unroll
        for (int w = 1; w < 8; w++) lse_merge(m, s, sm[w][c], ss[w][c]);
        float fi = 1.f / (1.f + c_eps[h]);
        out[h * NTOK + m0 + c] =
            fi * (logf(fmaxf(marg[h * NTOK + m0 + c], 1e-8f)) - (m + logf(s)));
    }
}

// ---------------- P application ----------------
__global__ void papply_kernel(const float* __restrict__ xres) {
    int h = blockIdx.y;
    int warp = threadIdx.x >> 5, lane = threadIdx.x & 31;
    int row = blockIdx.x * 8 + warp;
    __shared__ float lvs[NTOK];
    __shared__ float xs[3 * NTOK];
    __shared__ float vs[128 * 32];
    for (int i = threadIdx.x; i < NTOK; i += 256) lvs[i] = g_lv[h * NTOK + i];
    for (int i = threadIdx.x; i < 3 * NTOK; i += 256) xs[i] = xres[i];
    float lu_r = g_lu[h * NTOK + row];
    float acc = 0.f, ax = 0.f, psum = 0.f;
    for (int mc = 0; mc < NTOK; mc += 128) {
        __syncthreads();
        for (int i = threadIdx.x; i < 128 * 32; i += 256) {
            int r = i >> 5, d = i & 31;
            vs[i] = g_qkvg[(size_t)(mc + r) * (4*DMOD) + 2*DMOD + h * DH + d];
        }
        __syncthreads();
        const __half* lk = g_logKh + ((size_t)h * NTOK + row) * NTOK + mc;
#pragma unroll
        for (int mj = 0; mj < 128; mj += 32) {
            float pl = __expf(__half2float(lk[mj + lane]) + lvs[mc + mj + lane] + lu_r);
            psum += pl;
#pragma unroll
            for (int j = 0; j < 32; j++) {
                float p = __shfl_sync(0xffffffffu, pl, j);
                acc += p * vs[(mj + j) * 32 + lane];
                if (lane < 3) ax += p * xs[(mc + mj + j) * 3 + lane];
            }
        }
    }
    float ps = psum;
    for (int o = 16; o; o >>= 1) ps += __shfl_xor_sync(0xffffffffu, ps, o);
    float gt = g_qkvg[(size_t)row * (4*DMOD) + 3*DMOD + h * DH + lane];
    g_o[(size_t)row * DMOD + h * DH + lane] = acc / (1.f + __expf(-gt));
    if (lane < 3) g_xc[((size_t)h * NTOK + row) * 3 + lane] = ax;
    if (lane == 0) g_rows[h * NTOK + row] = ps;
}

__global__ void xout_kernel(const float* __restrict__ xres, const float* __restrict__ gamma,
                            float* __restrict__ out) {
    int n = blockIdx.x * 256 + threadIdx.x;
    if (n >= NTOK) return;
    float x0 = xres[n * 3 + 0], x1 = xres[n * 3 + 1], x2 = xres[n * 3 + 2];
    float a0 = 0.f, a1 = 0.f, a2 = 0.f;
    for (int h = 0; h < NH; h++) {
        float r = 1.f / (g_rows[h * NTOK + n] + 1e-8f);
        float gm = gamma[h];
        a0 += gm * (x0 - g_xc[((size_t)h * NTOK + n) * 3 + 0] * r);
        a1 += gm * (x1 - g_xc[((size_t)h * NTOK + n) * 3 + 1] * r);
        a2 += gm * (x2 - g_xc[((size_t)h * NTOK + n) * 3 + 2] * r);
    }
    out[n * 3 + 0] = x0 + a0;
    out[n * 3 + 1] = x1 + a1;
    out[n * 3 + 2] = x2 + a2;
}

__global__ void silumul_kernel() {
    int i = blockIdx.x * 256 + threadIdx.x;
    if (i < NTOK * DFF) {
        int n = i >> 11, j = i & (DFF - 1);
        float a = g_t12[(size_t)n * (2*DFF) + j];
        float b = g_t12[(size_t)n * (2*DFF) + DFF + j];
        g_t1[i] = a / (1.f + __expf(-a)) * b;
    }
}

// ---------------- launch ----------------
extern "C" void kernel_launch(void* const* d_in, const int* in_sizes, int n_in,
                              void* d_out, int out_size) {
    const float* h_in  = (const float*)d_in[0];
    const float* x_res = (const float*)d_in[1];
    const float* mu    = (const float*)d_in[2];
    const float* nu    = (const float*)d_in[3];
    const float* wrel  = (const float*)d_in[4];
    const float* wdist = (const float*)d_in[5];
    const float* ln_ag = (const float*)d_in[7];
    const float* ln_ab = (const float*)d_in[8];
    const float* Wq    = (const float*)d_in[9];
    const float* Wk    = (const float*)d_in[10];
    const float* Wv    = (const float*)d_in[11];
    const float* Wg    = (const float*)d_in[12];
    const float* Wo    = (const float*)d_in[13];
    const float* gamma = (const float*)d_in[14];
    const float* ln_fg = (const float*)d_in[15];
    const float* ln_fb = (const float*)d_in[16];
    const float* W1    = (const float*)d_in[17];
    const float* W2    = (const float*)d_in[18];
    const float* W3    = (const float*)d_in[19];
    float* out = (float*)d_out;

    float *p_hn, *p_qkvg, *p_lu, *p_lv, *p_o, *p_h2, *p_hf, *p_t1, *p_part, *p_t12;
    cudaGetSymbolAddress((void**)&p_hn,     g_hn);
    cudaGetSymbolAddress((void**)&p_qkvg,   g_qkvg);
    cudaGetSymbolAddress((void**)&p_lu,     g_lu);
    cudaGetSymbolAddress((void**)&p_lv,     g_lv);
    cudaGetSymbolAddress((void**)&p_o,      g_o);
    cudaGetSymbolAddress((void**)&p_h2,     g_h2);
    cudaGetSymbolAddress((void**)&p_hf,     g_hf);
    cudaGetSymbolAddress((void**)&p_t1,     g_t1);
    cudaGetSymbolAddress((void**)&p_part,   g_part);
    cudaGetSymbolAddress((void**)&p_t12,    g_t12);

    const int OUT_X  = NTOK * DMOD;
    const int OUT_LU = OUT_X + NTOK * 3;
    const int OUT_LV = OUT_LU + NH * NTOK;

    zero_kernel<<<(NH * NTOK + 1023) / 1024, 1024>>>(p_lv, NH * NTOK);
    ln_kernel<<<NTOK, 256>>>(h_in, ln_ag, ln_ab, p_hn);

    Ptr4 bqkvg; bqkvg.p[0] = Wq; bqkvg.p[1] = Wk; bqkvg.p[2] = Wv; bqkvg.p[3] = Wg;
    tc_gemm<<<dim3(4*DMOD/64, NTOK/128, 1), 256>>>(p_hn, bqkvg, p_qkvg, 4*DMOD, DMOD, DMOD, DMOD);

    qkln_kernel<<<dim3((NTOK * NH) / 8, 2), 256>>>(p_qkvg);

    build_logk<<<dim3(NTOK / 64, NTOK / 64, NH), 256>>>(wrel, x_res, wdist);

    dim3 grow(NTOK / 8, NH);
    dim3 gcol(NTOK / 64, NH);
    for (int it = 0; it < NITER; it++) {
        sinkhorn_row<<<grow, 256>>>(p_lv, mu, p_lu);
        sinkhorn_col<<<gcol, 256>>>(p_lu, nu, p_lv);
    }

    papply_kernel<<<grow, 256>>>(x_res);

    Ptr4 bWo; bWo.p[0] = Wo; bWo.p[1] = Wo; bWo.p[2] = Wo; bWo.p[3] = Wo;
    tc_gemm<<<dim3(DMOD/64, NTOK/128, 2), 256>>>(p_o, bWo, p_part, DMOD, DMOD, DMOD, DMOD/2);
    reduce_add<<<(NTOK*DMOD)/256, 256>>>(h_in, p_part, 2, p_h2, NTOK*DMOD);

    xout_kernel<<<(NTOK + 255) / 256, 256>>>(x_res, gamma, out + OUT_X);

    ln_kernel<<<NTOK, 256>>>(p_h2, ln_fg, ln_fb, p_hf);
    Ptr4 b12; b12.p[0] = W1; b12.p[1] = W2; b12.p[2] = W1; b12.p[3] = W1;
    tc_gemm<<<dim3(2*DFF/64, NTOK/128, 1), 256>>>(p_hf, b12, p_t12, 2*DFF, DMOD, DFF, DMOD);
    silumul_kernel<<<(NTOK * DFF) / 256, 256>>>();
    Ptr4 bW3; bW3.p[0] = W3; bW3.p[1] = W3; bW3.p[2] = W3; bW3.p[3] = W3;
    tc_gemm<<<dim3(DMOD/64, NTOK/128, 4), 256>>>(p_t1, bW3, p_part, DMOD, DFF, DMOD, DFF/4);
    reduce_add<<<(NTOK*DMOD)/256, 256>>>(p_h2, p_part, 4, out, NTOK*DMOD);

    copy_uv_kernel<<<(NH * NTOK + 1023) / 1024, 1024>>>(p_lu, p_lv, out + OUT_LU, out + OUT_LV);
}

// round 7
// speedup vs baseline: 1.1652x; 1.1652x over previous
#include <cuda_runtime.h>
#include <cuda_fp16.h>
#include <cuda_bf16.h>
#include <math.h>

#define NTOK 1280
#define DMOD 512
#define NH   16
#define DH   32
#define DFF  2048
#define NITER 20

// ---------------- scratch ----------------
__device__ __nv_bfloat16 g_EK[NH*NTOK*NTOK];  // exp(logK), bf16
__device__ float g_hn  [NTOK*DMOD];
__device__ float g_qkvg[NTOK*4*DMOD];         // [q | k | v | gate]
__device__ float g_lu [NH*NTOK];
__device__ float g_lv [NH*NTOK];
__device__ float g_eu [NH*NTOK];              // exp(lu)
__device__ float g_ev [NH*NTOK];              // exp(lv)
__device__ float g_xc [NH*NTOK*3];
__device__ float g_rows[NH*NTOK];
__device__ float g_o  [NTOK*DMOD];
__device__ float g_h2 [NTOK*DMOD];
__device__ float g_hf [NTOK*DMOD];
__device__ float g_t12[NTOK*2*DFF];           // [t1 | t2]
__device__ float g_t1 [NTOK*DFF];
__device__ float g_part[4*NTOK*DMOD];         // split-K partials

__constant__ float c_eps[NH] = {0.5f,0.5f,0.5f,0.5f, 1.f,1.f,1.f,1.f,
                                2.f,2.f,2.f,2.f, 4.f,4.f,4.f,4.f};

struct Ptr4 { const float* p[4]; };

// ---------------- utility kernels ----------------
__global__ void ones_kernel(float* p, int n) {
    int i = blockIdx.x * blockDim.x + threadIdx.x;
    if (i < n) p[i] = 1.f;
}

__global__ void copy_uv_kernel(const float* __restrict__ lu, const float* __restrict__ lv,
                               float* __restrict__ o1, float* __restrict__ o2) {
    int i = blockIdx.x * blockDim.x + threadIdx.x;
    if (i < NH*NTOK) { o1[i] = lu[i]; o2[i] = lv[i]; }
}

__global__ void ln_kernel(const float* __restrict__ in, const float* __restrict__ g,
                          const float* __restrict__ b, float* __restrict__ out) {
    int row = blockIdx.x;
    int t = threadIdx.x;
    const float* x = in + (size_t)row * DMOD;
    float v0 = x[t], v1 = x[t + 256];
    __shared__ float red[256];
    red[t] = v0 + v1;
    __syncthreads();
    for (int o = 128; o > 0; o >>= 1) { if (t < o) red[t] += red[t + o]; __syncthreads(); }
    float mean = red[0] * (1.f / DMOD);
    __syncthreads();
    float d0 = v0 - mean, d1 = v1 - mean;
    red[t] = d0 * d0 + d1 * d1;
    __syncthreads();
    for (int o = 128; o > 0; o >>= 1) { if (t < o) red[t] += red[t + o]; __syncthreads(); }
    float r = rsqrtf(red[0] * (1.f / DMOD) + 1e-5f);
    out[(size_t)row * DMOD + t]       = d0 * r * g[t]       + b[t];
    out[(size_t)row * DMOD + t + 256] = d1 * r * g[t + 256] + b[t + 256];
}

// per-head QK layernorm; blockIdx.y selects Q (0) or K (1); row stride 4*DMOD
__global__ void qkln_kernel(float* __restrict__ base) {
    int gidx = blockIdx.x * 8 + (threadIdx.x >> 5);
    int lane = threadIdx.x & 31;
    if (gidx >= NTOK * NH) return;
    int n = gidx / NH, h = gidx % NH;
    float* p = base + (size_t)n * (4*DMOD) + blockIdx.y * DMOD + h * DH;
    float v = p[lane];
    float s = v;
    for (int o = 16; o; o >>= 1) s += __shfl_xor_sync(0xffffffffu, s, o);
    float mean = s * (1.f / 32.f);
    float d = v - mean;
    float s2 = d * d;
    for (int o = 16; o; o >>= 1) s2 += __shfl_xor_sync(0xffffffffu, s2, o);
    p[lane] = d * rsqrtf(s2 * (1.f / 32.f) + 1e-5f);
}

// ---------------- TF32 tensor-core GEMM ----------------
__device__ __forceinline__ unsigned f2tf32(float f) {
    unsigned u;
    asm("cvt.rna.tf32.f32 %0, %1;" : "=r"(u) : "f"(f));
    return u;
}

__device__ __forceinline__ void mma_tf32(float c[4], const unsigned a[4], const unsigned b[2]) {
    asm volatile("mma.sync.aligned.m16n8k8.row.col.f32.tf32.tf32.f32 "
        "{%0,%1,%2,%3}, {%4,%5,%6,%7}, {%8,%9}, {%0,%1,%2,%3};"
        : "+f"(c[0]), "+f"(c[1]), "+f"(c[2]), "+f"(c[3])
        : "r"(a[0]), "r"(a[1]), "r"(a[2]), "r"(a[3]), "r"(b[0]), "r"(b[1]));
}

// C[M=1280, Nn] = A[1280,K] @ Bsel[Nn,K]^T, output to C + blockIdx.z*1280*Nn.
__global__ void tc_gemm(const float* __restrict__ A, Ptr4 B4, float* __restrict__ C,
                        int Nn, int K, int colsPer, int KC) {
    __shared__ float As[32][136];
    __shared__ float Bs[32][72];
    int tid = threadIdx.x;
    int m0 = blockIdx.y * 128, n0 = blockIdx.x * 64;
    const float* B = B4.p[n0 / colsPer] + (size_t)(n0 % colsPer) * K;
    int kbeg = blockIdx.z * KC, kend = kbeg + KC;

    int arow = tid >> 1, akseg = (tid & 1) << 4;
    int brow = tid & 63, bkseg = (tid >> 6) << 3;
    const float* Ap = A + (size_t)(m0 + arow) * K + akseg;
    const float* Bp = B + (size_t)brow * K + bkseg;

    int lane = tid & 31, g = lane >> 2, t = lane & 3;
    int wm = tid >> 6;
    int wn = (tid >> 5) & 1;
    int mBase = wm * 32, nBase = wn * 32;

    float c[2][4][4];
#pragma unroll
    for (int mi = 0; mi < 2; mi++)
#pragma unroll
        for (int ni = 0; ni < 4; ni++)
#pragma unroll
            for (int r = 0; r < 4; r++) c[mi][ni][r] = 0.f;

    for (int k0 = kbeg; k0 < kend; k0 += 32) {
        __syncthreads();
#pragma unroll
        for (int i = 0; i < 4; i++) {
            float4 a4 = *(const float4*)(Ap + k0 + 4 * i);
            As[akseg + 4*i + 0][arow] = __uint_as_float(f2tf32(a4.x));
            As[akseg + 4*i + 1][arow] = __uint_as_float(f2tf32(a4.y));
            As[akseg + 4*i + 2][arow] = __uint_as_float(f2tf32(a4.z));
            As[akseg + 4*i + 3][arow] = __uint_as_float(f2tf32(a4.w));
        }
#pragma unroll
        for (int i = 0; i < 2; i++) {
            float4 b4 = *(const float4*)(Bp + k0 + 4 * i);
            Bs[bkseg + 4*i + 0][brow] = __uint_as_float(f2tf32(b4.x));
            Bs[bkseg + 4*i + 1][brow] = __uint_as_float(f2tf32(b4.y));
            Bs[bkseg + 4*i + 2][brow] = __uint_as_float(f2tf32(b4.z));
            Bs[bkseg + 4*i + 3][brow] = __uint_as_float(f2tf32(b4.w));
        }
        __syncthreads();
#pragma unroll
        for (int ks = 0; ks < 32; ks += 8) {
            unsigned a[2][4], b[4][2];
#pragma unroll
            for (int mi = 0; mi < 2; mi++) {
                int mo = mBase + mi * 16 + g;
                a[mi][0] = __float_as_uint(As[ks + t][mo]);
                a[mi][1] = __float_as_uint(As[ks + t][mo + 8]);
                a[mi][2] = __float_as_uint(As[ks + t + 4][mo]);
                a[mi][3] = __float_as_uint(As[ks + t + 4][mo + 8]);
            }
#pragma unroll
            for (int ni = 0; ni < 4; ni++) {
                int no = nBase + ni * 8 + g;
                b[ni][0] = __float_as_uint(Bs[ks + t][no]);
                b[ni][1] = __float_as_uint(Bs[ks + t + 4][no]);
            }
#pragma unroll
            for (int mi = 0; mi < 2; mi++)
#pragma unroll
                for (int ni = 0; ni < 4; ni++)
                    mma_tf32(c[mi][ni], a[mi], b[ni]);
        }
    }

    float* Co = C + (size_t)blockIdx.z * NTOK * Nn;
#pragma unroll
    for (int mi = 0; mi < 2; mi++) {
        int r0 = m0 + mBase + mi * 16 + g;
#pragma unroll
        for (int ni = 0; ni < 4; ni++) {
            int col = n0 + nBase + ni * 8 + 2 * t;
            *(float2*)(Co + (size_t)r0 * Nn + col)       = make_float2(c[mi][ni][0], c[mi][ni][1]);
            *(float2*)(Co + (size_t)(r0 + 8) * Nn + col) = make_float2(c[mi][ni][2], c[mi][ni][3]);
        }
    }
}

__global__ void reduce_add(const float* __restrict__ R, const float* __restrict__ part,
                           int Z, float* __restrict__ out, int n) {
    int i = blockIdx.x * 256 + threadIdx.x;
    if (i >= n) return;
    float a = R[i];
    for (int z = 0; z < Z; z++) a += part[(size_t)z * n + i];
    out[i] = a;
}

// ---------------- build EK = exp(logK) in bf16 ----------------
__global__ void build_logk(const float* __restrict__ wrel, const float* __restrict__ xres,
                           const float* __restrict__ wdist) {
    __shared__ float Qs[32][68];
    __shared__ float Ks[32][68];
    __shared__ float xa[64][3], xb[64][3];
    int h = blockIdx.z;
    int n0 = blockIdx.y * 64, m0 = blockIdx.x * 64;
    int t = threadIdx.x;

    {
        int r = t >> 2, seg = (t & 3) << 3;
        const float* qp = g_qkvg + (size_t)(n0 + r) * (4*DMOD) + h * DH + seg;
        const float* kp = g_qkvg + (size_t)(m0 + r) * (4*DMOD) + DMOD + h * DH + seg;
#pragma unroll
        for (int i = 0; i < 2; i++) {
            float4 q4 = *(const float4*)(qp + 4*i);
            float4 k4 = *(const float4*)(kp + 4*i);
            Qs[seg + 4*i + 0][r] = q4.x; Qs[seg + 4*i + 1][r] = q4.y;
            Qs[seg + 4*i + 2][r] = q4.z; Qs[seg + 4*i + 3][r] = q4.w;
            Ks[seg + 4*i + 0][r] = k4.x; Ks[seg + 4*i + 1][r] = k4.y;
            Ks[seg + 4*i + 2][r] = k4.z; Ks[seg + 4*i + 3][r] = k4.w;
        }
    }
    if (t < 192) { int r = t / 3, c = t % 3; xa[r][c] = xres[(n0 + r) * 3 + c]; }
    if (t >= 64 && t < 256) {
        int u = t - 64;
        if (u < 192) { int r = u / 3, c = u % 3; xb[r][c] = xres[(m0 + r) * 3 + c]; }
    }
    __syncthreads();

    int tm = t >> 4, tn = t & 15;
    float acc[4][4] = {};
#pragma unroll
    for (int k = 0; k < 32; k++) {
        float4 av = *(const float4*)&Qs[k][tm << 2];
        float4 bv = *(const float4*)&Ks[k][tn << 2];
        float a[4] = {av.x, av.y, av.z, av.w};
        float bb[4] = {bv.x, bv.y, bv.z, bv.w};
#pragma unroll
        for (int i = 0; i < 4; i++)
#pragma unroll
            for (int j = 0; j < 4; j++) acc[i][j] += a[i] * bb[j];
    }

    float inve = 1.f / c_eps[h];
    float wd = wdist[h] * 0.01f;
    const float scale = 0.17677669529663687f;
#pragma unroll
    for (int i = 0; i < 4; i++) {
        int nl = (tm << 2) + i;
        int n = n0 + nl;
        float ax0 = xa[nl][0], ax1 = xa[nl][1], ax2 = xa[nl][2];
        size_t base = ((size_t)h * NTOK + n) * NTOK + m0 + (tn << 2);
        float4 w4 = *(const float4*)(wrel + base);
        float e[4];
#pragma unroll
        for (int j = 0; j < 4; j++) {
            int ml = (tn << 2) + j;
            float dx = ax0 - xb[ml][0];
            float dy = ax1 - xb[ml][1];
            float dz = ax2 - xb[ml][2];
            float d2 = dx * dx + dy * dy + dz * dz;
            float wr = (j == 0) ? w4.x : (j == 1) ? w4.y : (j == 2) ? w4.z : w4.w;
            e[j] = __expf((acc[i][j] * scale + wr - wd * d2) * inve);
        }
        *(__nv_bfloat162*)(g_EK + base)     = __floats2bfloat162_rn(e[0], e[1]);
        *(__nv_bfloat162*)(g_EK + base + 2) = __floats2bfloat162_rn(e[2], e[3]);
    }
}

// ---------------- Sinkhorn as GEMV ----------------
// row pass: S_n = sum_m EK[h,n,m]*ev[h,m]; lu = fi*(log(mu)-log(S)); eu = exp(lu)
__global__ void sink_row(const float* __restrict__ mu) {
    int h = blockIdx.y;
    __shared__ float evs[NTOK];
    for (int i = threadIdx.x; i < NTOK; i += 256) evs[i] = g_ev[h * NTOK + i];
    __syncthreads();
    int warp = threadIdx.x >> 5, lane = threadIdx.x & 31;
    int row = blockIdx.x * 8 + warp;
    const uint4* pv = (const uint4*)(g_EK + ((size_t)h * NTOK + row) * NTOK);
    float acc = 0.f;
#pragma unroll
    for (int c = 0; c < 5; c++) {
        uint4 u = pv[c * 32 + lane];
        int jb = (c * 32 + lane) * 8;
        const __nv_bfloat162* hh = (const __nv_bfloat162*)&u;
        float2 f0 = __bfloat1622float2(hh[0]);
        float2 f1 = __bfloat1622float2(hh[1]);
        float2 f2 = __bfloat1622float2(hh[2]);
        float2 f3 = __bfloat1622float2(hh[3]);
        acc += f0.x * evs[jb + 0] + f0.y * evs[jb + 1]
             + f1.x * evs[jb + 2] + f1.y * evs[jb + 3]
             + f2.x * evs[jb + 4] + f2.y * evs[jb + 5]
             + f3.x * evs[jb + 6] + f3.y * evs[jb + 7];
    }
    for (int o = 16; o; o >>= 1) acc += __shfl_xor_sync(0xffffffffu, acc, o);
    if (lane == 0) {
        float fi = 1.f / (1.f + c_eps[h]);
        float lu = fi * (logf(fmaxf(mu[h * NTOK + row], 1e-8f)) - logf(acc));
        g_lu[h * NTOK + row] = lu;
        g_eu[h * NTOK + row] = __expf(lu);
    }
}

// col pass: S_m = sum_n EK[h,n,m]*eu[h,n]; lv = fi*(log(nu)-log(S)); ev = exp(lv)
// grid (NTOK/64, NH); warp w handles rows [w*160,(w+1)*160) of this block's 64 cols.
__global__ void sink_col(const float* __restrict__ nu) {
    int h = blockIdx.y;
    int m0 = blockIdx.x * 64;
    __shared__ float eus[NTOK];
    __shared__ float ssum[8][64];
    for (int i = threadIdx.x; i < NTOK; i += 256) eus[i] = g_eu[h * NTOK + i];
    __syncthreads();
    int warp = threadIdx.x >> 5, lane = threadIdx.x & 31;
    int r0 = warp * 160;
    const __nv_bfloat162* p =
        (const __nv_bfloat162*)(g_EK + ((size_t)h * NTOK + r0) * NTOK + m0) + lane;
    const int STRIDE2 = NTOK / 2;
    float sa = 0.f, sb = 0.f;
#pragma unroll 4
    for (int r = 0; r < 160; r++) {
        float2 f = __bfloat1622float2(p[(size_t)r * STRIDE2]);
        float e = eus[r0 + r];
        sa += f.x * e;
        sb += f.y * e;
    }
    ssum[warp][2*lane]   = sa;
    ssum[warp][2*lane+1] = sb;
    __syncthreads();
    if (threadIdx.x < 64) {
        int c = threadIdx.x;
        float S = ssum[0][c];
#pragma unroll
        for (int w = 1; w < 8; w++) S += ssum[w][c];
        float fi = 1.f / (1.f + c_eps[h]);
        float lv = fi * (logf(fmaxf(nu[h * NTOK + m0 + c], 1e-8f)) - logf(S));
        g_lv[h * NTOK + m0 + c] = lv;
        g_ev[h * NTOK + m0 + c] = __expf(lv);
    }
}

// ---------------- P application: P = eu*EK*ev ----------------
__global__ void papply_kernel(const float* __restrict__ xres) {
    int h = blockIdx.y;
    int warp = threadIdx.x >> 5, lane = threadIdx.x & 31;
    int row = blockIdx.x * 8 + warp;
    __shared__ float evs[NTOK];
    __shared__ float xs[3 * NTOK];
    __shared__ float vs[128 * 32];
    for (int i = threadIdx.x; i < NTOK; i += 256) evs[i] = g_ev[h * NTOK + i];
    for (int i = threadIdx.x; i < 3 * NTOK; i += 256) xs[i] = xres[i];
    float eu_r = g_eu[h * NTOK + row];
    float acc = 0.f, ax = 0.f, psum = 0.f;
    for (int mc = 0; mc < NTOK; mc += 128) {
        __syncthreads();
        for (int i = threadIdx.x; i < 128 * 32; i += 256) {
            int r = i >> 5, d = i & 31;
            vs[i] = g_qkvg[(size_t)(mc + r) * (4*DMOD) + 2*DMOD + h * DH + d];
        }
        __syncthreads();
        const __nv_bfloat16* lk = g_EK + ((size_t)h * NTOK + row) * NTOK + mc;
#pragma unroll
        for (int mj = 0; mj < 128; mj += 32) {
            float pl = eu_r * __bfloat162float(lk[mj + lane]) * evs[mc + mj + lane];
            psum += pl;
#pragma unroll
            for (int j = 0; j < 32; j++) {
                float p = __shfl_sync(0xffffffffu, pl, j);
                acc += p * vs[(mj + j) * 32 + lane];
                if (lane < 3) ax += p * xs[(mc + mj + j) * 3 + lane];
            }
        }
    }
    float ps = psum;
    for (int o = 16; o; o >>= 1) ps += __shfl_xor_sync(0xffffffffu, ps, o);
    float gt = g_qkvg[(size_t)row * (4*DMOD) + 3*DMOD + h * DH + lane];
    g_o[(size_t)row * DMOD + h * DH + lane] = acc / (1.f + __expf(-gt));
    if (lane < 3) g_xc[((size_t)h * NTOK + row) * 3 + lane] = ax;
    if (lane == 0) g_rows[h * NTOK + row] = ps;
}

__global__ void xout_kernel(const float* __restrict__ xres, const float* __restrict__ gamma,
                            float* __restrict__ out) {
    int n = blockIdx.x * 256 + threadIdx.x;
    if (n >= NTOK) return;
    float x0 = xres[n * 3 + 0], x1 = xres[n * 3 + 1], x2 = xres[n * 3 + 2];
    float a0 = 0.f, a1 = 0.f, a2 = 0.f;
    for (int h = 0; h < NH; h++) {
        float r = 1.f / (g_rows[h * NTOK + n] + 1e-8f);
        float gm = gamma[h];
        a0 += gm * (x0 - g_xc[((size_t)h * NTOK + n) * 3 + 0] * r);
        a1 += gm * (x1 - g_xc[((size_t)h * NTOK + n) * 3 + 1] * r);
        a2 += gm * (x2 - g_xc[((size_t)h * NTOK + n) * 3 + 2] * r);
    }
    out[n * 3 + 0] = x0 + a0;
    out[n * 3 + 1] = x1 + a1;
    out[n * 3 + 2] = x2 + a2;
}

__global__ void silumul_kernel() {
    int i = blockIdx.x * 256 + threadIdx.x;
    if (i < NTOK * DFF) {
        int n = i >> 11, j = i & (DFF - 1);
        float a = g_t12[(size_t)n * (2*DFF) + j];
        float b = g_t12[(size_t)n * (2*DFF) + DFF + j];
        g_t1[i] = a / (1.f + __expf(-a)) * b;
    }
}

// ---------------- launch ----------------
extern "C" void kernel_launch(void* const* d_in, const int* in_sizes, int n_in,
                              void* d_out, int out_size) {
    const float* h_in  = (const float*)d_in[0];
    const float* x_res = (const float*)d_in[1];
    const float* mu    = (const float*)d_in[2];
    const float* nu    = (const float*)d_in[3];
    const float* wrel  = (const float*)d_in[4];
    const float* wdist = (const float*)d_in[5];
    const float* ln_ag = (const float*)d_in[7];
    const float* ln_ab = (const float*)d_in[8];
    const float* Wq    = (const float*)d_in[9];
    const float* Wk    = (const float*)d_in[10];
    const float* Wv    = (const float*)d_in[11];
    const float* Wg    = (const float*)d_in[12];
    const float* Wo    = (const float*)d_in[13];
    const float* gamma = (const float*)d_in[14];
    const float* ln_fg = (const float*)d_in[15];
    const float* ln_fb = (const float*)d_in[16];
    const float* W1    = (const float*)d_in[17];
    const float* W2    = (const float*)d_in[18];
    const float* W3    = (const float*)d_in[19];
    float* out = (float*)d_out;

    float *p_hn, *p_qkvg, *p_lu, *p_lv, *p_ev, *p_o, *p_h2, *p_hf, *p_t1, *p_part, *p_t12;
    cudaGetSymbolAddress((void**)&p_hn,     g_hn);
    cudaGetSymbolAddress((void**)&p_qkvg,   g_qkvg);
    cudaGetSymbolAddress((void**)&p_lu,     g_lu);
    cudaGetSymbolAddress((void**)&p_lv,     g_lv);
    cudaGetSymbolAddress((void**)&p_ev,     g_ev);
    cudaGetSymbolAddress((void**)&p_o,      g_o);
    cudaGetSymbolAddress((void**)&p_h2,     g_h2);
    cudaGetSymbolAddress((void**)&p_hf,     g_hf);
    cudaGetSymbolAddress((void**)&p_t1,     g_t1);
    cudaGetSymbolAddress((void**)&p_part,   g_part);
    cudaGetSymbolAddress((void**)&p_t12,    g_t12);

    const int OUT_X  = NTOK * DMOD;
    const int OUT_LU = OUT_X + NTOK * 3;
    const int OUT_LV = OUT_LU + NH * NTOK;

    ones_kernel<<<(NH * NTOK + 1023) / 1024, 1024>>>(p_ev, NH * NTOK);  // ev = exp(0)
    ln_kernel<<<NTOK, 256>>>(h_in, ln_ag, ln_ab, p_hn);

    Ptr4 bqkvg; bqkvg.p[0] = Wq; bqkvg.p[1] = Wk; bqkvg.p[2] = Wv; bqkvg.p[3] = Wg;
    tc_gemm<<<dim3(4*DMOD/64, NTOK/128, 1), 256>>>(p_hn, bqkvg, p_qkvg, 4*DMOD, DMOD, DMOD, DMOD);

    qkln_kernel<<<dim3((NTOK * NH) / 8, 2), 256>>>(p_qkvg);

    build_logk<<<dim3(NTOK / 64, NTOK / 64, NH), 256>>>(wrel, x_res, wdist);

    dim3 grow(NTOK / 8, NH);
    dim3 gcol(NTOK / 64, NH);
    for (int it = 0; it < NITER; it++) {
        sink_row<<<grow, 256>>>(mu);
        sink_col<<<gcol, 256>>>(nu);
    }

    papply_kernel<<<grow, 256>>>(x_res);

    Ptr4 bWo; bWo.p[0] = Wo; bWo.p[1] = Wo; bWo.p[2] = Wo; bWo.p[3] = Wo;
    tc_gemm<<<dim3(DMOD/64, NTOK/128, 2), 256>>>(p_o, bWo, p_part, DMOD, DMOD, DMOD, DMOD/2);
    reduce_add<<<(NTOK*DMOD)/256, 256>>>(h_in, p_part, 2, p_h2, NTOK*DMOD);

    xout_kernel<<<(NTOK + 255) / 256, 256>>>(x_res, gamma, out + OUT_X);

    ln_kernel<<<NTOK, 256>>>(p_h2, ln_fg, ln_fb, p_hf);
    Ptr4 b12; b12.p[0] = W1; b12.p[1] = W2; b12.p[2] = W1; b12.p[3] = W1;
    tc_gemm<<<dim3(2*DFF/64, NTOK/128, 1), 256>>>(p_hf, b12, p_t12, 2*DFF, DMOD, DFF, DMOD);
    silumul_kernel<<<(NTOK * DFF) / 256, 256>>>();
    Ptr4 bW3; bW3.p[0] = W3; bW3.p[1] = W3; bW3.p[2] = W3; bW3.p[3] = W3;
    tc_gemm<<<dim3(DMOD/64, NTOK/128, 4), 256>>>(p_t1, bW3, p_part, DMOD, DFF, DMOD, DFF/4);
    reduce_add<<<(NTOK*DMOD)/256, 256>>>(p_h2, p_part, 4, out, NTOK*DMOD);

    copy_uv_kernel<<<(NH * NTOK + 1023) / 1024, 1024>>>(p_lu, p_lv, out + OUT_LU, out + OUT_LV);
}

// round 9
// speedup vs baseline: 1.2876x; 1.1050x over previous
#include <cuda_runtime.h>
#include <cuda_fp16.h>
#include <cuda_bf16.h>
#include <math.h>

#define NTOK 1280
#define DMOD 512
#define NH   16
#define DH   32
#define DFF  2048
#define NITER 20
#define NSTRIPE 16
#define ROWS_PER_STRIPE 80   // 16*80 = 1280
#define ROWS_PER_WARP 10     // 8 warps * 10 = 80

// ---------------- scratch ----------------
__device__ __nv_bfloat16 g_EK[NH*NTOK*NTOK];  // exp(logK), bf16
__device__ float g_hn  [NTOK*DMOD];
__device__ float g_qkvg[NTOK*4*DMOD];         // [q | k | v | gate]
__device__ float g_lu [NH*NTOK];
__device__ float g_lv [NH*NTOK];
__device__ float g_eu [NH*NTOK];              // exp(lu)
__device__ float g_ev [NH*NTOK];              // exp(lv)
__device__ float g_xc [NH*NTOK*3];
__device__ float g_rows[NH*NTOK];
__device__ float g_o  [NTOK*DMOD];
__device__ float g_h2 [NTOK*DMOD];
__device__ float g_hf [NTOK*DMOD];
__device__ float g_t12[NTOK*2*DFF];           // [t1 | t2]
__device__ float g_t1 [NTOK*DFF];
__device__ float g_part[4*NTOK*DMOD];         // split-K partials / sinkhorn col partials

__constant__ float c_eps[NH] = {0.5f,0.5f,0.5f,0.5f, 1.f,1.f,1.f,1.f,
                                2.f,2.f,2.f,2.f, 4.f,4.f,4.f,4.f};

struct Ptr4 { const float* p[4]; };

// ---------------- utility kernels ----------------
__global__ void ones_kernel(float* p, int n) {
    int i = blockIdx.x * blockDim.x + threadIdx.x;
    if (i < n) p[i] = 1.f;
}

__global__ void copy_uv_kernel(const float* __restrict__ lu, const float* __restrict__ lv,
                               float* __restrict__ o1, float* __restrict__ o2) {
    int i = blockIdx.x * blockDim.x + threadIdx.x;
    if (i < NH*NTOK) { o1[i] = lu[i]; o2[i] = lv[i]; }
}

__global__ void ln_kernel(const float* __restrict__ in, const float* __restrict__ g,
                          const float* __restrict__ b, float* __restrict__ out) {
    int row = blockIdx.x;
    int t = threadIdx.x;
    const float* x = in + (size_t)row * DMOD;
    float v0 = x[t], v1 = x[t + 256];
    __shared__ float red[256];
    red[t] = v0 + v1;
    __syncthreads();
    for (int o = 128; o > 0; o >>= 1) { if (t < o) red[t] += red[t + o]; __syncthreads(); }
    float mean = red[0] * (1.f / DMOD);
    __syncthreads();
    float d0 = v0 - mean, d1 = v1 - mean;
    red[t] = d0 * d0 + d1 * d1;
    __syncthreads();
    for (int o = 128; o > 0; o >>= 1) { if (t < o) red[t] += red[t + o]; __syncthreads(); }
    float r = rsqrtf(red[0] * (1.f / DMOD) + 1e-5f);
    out[(size_t)row * DMOD + t]       = d0 * r * g[t]       + b[t];
    out[(size_t)row * DMOD + t + 256] = d1 * r * g[t + 256] + b[t + 256];
}

__global__ void qkln_kernel(float* __restrict__ base) {
    int gidx = blockIdx.x * 8 + (threadIdx.x >> 5);
    int lane = threadIdx.x & 31;
    if (gidx >= NTOK * NH) return;
    int n = gidx / NH, h = gidx % NH;
    float* p = base + (size_t)n * (4*DMOD) + blockIdx.y * DMOD + h * DH;
    float v = p[lane];
    float s = v;
    for (int o = 16; o; o >>= 1) s += __shfl_xor_sync(0xffffffffu, s, o);
    float mean = s * (1.f / 32.f);
    float d = v - mean;
    float s2 = d * d;
    for (int o = 16; o; o >>= 1) s2 += __shfl_xor_sync(0xffffffffu, s2, o);
    p[lane] = d * rsqrtf(s2 * (1.f / 32.f) + 1e-5f);
}

// ---------------- TF32 tensor-core GEMM ----------------
__device__ __forceinline__ unsigned f2tf32(float f) {
    unsigned u;
    asm("cvt.rna.tf32.f32 %0, %1;" : "=r"(u) : "f"(f));
    return u;
}

__device__ __forceinline__ void mma_tf32(float c[4], const unsigned a[4], const unsigned b[2]) {
    asm volatile("mma.sync.aligned.m16n8k8.row.col.f32.tf32.tf32.f32 "
        "{%0,%1,%2,%3}, {%4,%5,%6,%7}, {%8,%9}, {%0,%1,%2,%3};"
        : "+f"(c[0]), "+f"(c[1]), "+f"(c[2]), "+f"(c[3])
        : "r"(a[0]), "r"(a[1]), "r"(a[2]), "r"(a[3]), "r"(b[0]), "r"(b[1]));
}

__global__ void tc_gemm(const float* __restrict__ A, Ptr4 B4, float* __restrict__ C,
                        int Nn, int K, int colsPer, int KC) {
    __shared__ float As[32][136];
    __shared__ float Bs[32][72];
    int tid = threadIdx.x;
    int m0 = blockIdx.y * 128, n0 = blockIdx.x * 64;
    const float* B = B4.p[n0 / colsPer] + (size_t)(n0 % colsPer) * K;
    int kbeg = blockIdx.z * KC, kend = kbeg + KC;

    int arow = tid >> 1, akseg = (tid & 1) << 4;
    int brow = tid & 63, bkseg = (tid >> 6) << 3;
    const float* Ap = A + (size_t)(m0 + arow) * K + akseg;
    const float* Bp = B + (size_t)brow * K + bkseg;

    int lane = tid & 31, g = lane >> 2, t = lane & 3;
    int wm = tid >> 6;
    int wn = (tid >> 5) & 1;
    int mBase = wm * 32, nBase = wn * 32;

    float c[2][4][4];
#pragma unroll
    for (int mi = 0; mi < 2; mi++)
#pragma unroll
        for (int ni = 0; ni < 4; ni++)
#pragma unroll
            for (int r = 0; r < 4; r++) c[mi][ni][r] = 0.f;

    for (int k0 = kbeg; k0 < kend; k0 += 32) {
        __syncthreads();
#pragma unroll
        for (int i = 0; i < 4; i++) {
            float4 a4 = *(const float4*)(Ap + k0 + 4 * i);
            As[akseg + 4*i + 0][arow] = __uint_as_float(f2tf32(a4.x));
            As[akseg + 4*i + 1][arow] = __uint_as_float(f2tf32(a4.y));
            As[akseg + 4*i + 2][arow] = __uint_as_float(f2tf32(a4.z));
            As[akseg + 4*i + 3][arow] = __uint_as_float(f2tf32(a4.w));
        }
#pragma unroll
        for (int i = 0; i < 2; i++) {
            float4 b4 = *(const float4*)(Bp + k0 + 4 * i);
            Bs[bkseg + 4*i + 0][brow] = __uint_as_float(f2tf32(b4.x));
            Bs[bkseg + 4*i + 1][brow] = __uint_as_float(f2tf32(b4.y));
            Bs[bkseg + 4*i + 2][brow] = __uint_as_float(f2tf32(b4.z));
            Bs[bkseg + 4*i + 3][brow] = __uint_as_float(f2tf32(b4.w));
        }
        __syncthreads();
#pragma unroll
        for (int ks = 0; ks < 32; ks += 8) {
            unsigned a[2][4], b[4][2];
#pragma unroll
            for (int mi = 0; mi < 2; mi++) {
                int mo = mBase + mi * 16 + g;
                a[mi][0] = __float_as_uint(As[ks + t][mo]);
                a[mi][1] = __float_as_uint(As[ks + t][mo + 8]);
                a[mi][2] = __float_as_uint(As[ks + t + 4][mo]);
                a[mi][3] = __float_as_uint(As[ks + t + 4][mo + 8]);
            }
#pragma unroll
            for (int ni = 0; ni < 4; ni++) {
                int no = nBase + ni * 8 + g;
                b[ni][0] = __float_as_uint(Bs[ks + t][no]);
                b[ni][1] = __float_as_uint(Bs[ks + t + 4][no]);
            }
#pragma unroll
            for (int mi = 0; mi < 2; mi++)
#pragma unroll
                for (int ni = 0; ni < 4; ni++)
                    mma_tf32(c[mi][ni], a[mi], b[ni]);
        }
    }

    float* Co = C + (size_t)blockIdx.z * NTOK * Nn;
#pragma unroll
    for (int mi = 0; mi < 2; mi++) {
        int r0 = m0 + mBase + mi * 16 + g;
#pragma unroll
        for (int ni = 0; ni < 4; ni++) {
            int col = n0 + nBase + ni * 8 + 2 * t;
            *(float2*)(Co + (size_t)r0 * Nn + col)       = make_float2(c[mi][ni][0], c[mi][ni][1]);
            *(float2*)(Co + (size_t)(r0 + 8) * Nn + col) = make_float2(c[mi][ni][2], c[mi][ni][3]);
        }
    }
}

__global__ void reduce_add(const float* __restrict__ R, const float* __restrict__ part,
                           int Z, float* __restrict__ out, int n) {
    int i = blockIdx.x * 256 + threadIdx.x;
    if (i >= n) return;
    float a = R[i];
    for (int z = 0; z < Z; z++) a += part[(size_t)z * n + i];
    out[i] = a;
}

// ---------------- build EK = exp(logK) in bf16 ----------------
__global__ void build_logk(const float* __restrict__ wrel, const float* __restrict__ xres,
                           const float* __restrict__ wdist) {
    __shared__ float Qs[32][68];
    __shared__ float Ks[32][68];
    __shared__ float xa[64][3], xb[64][3];
    int h = blockIdx.z;
    int n0 = blockIdx.y * 64, m0 = blockIdx.x * 64;
    int t = threadIdx.x;

    {
        int r = t >> 2, seg = (t & 3) << 3;
        const float* qp = g_qkvg + (size_t)(n0 + r) * (4*DMOD) + h * DH + seg;
        const float* kp = g_qkvg + (size_t)(m0 + r) * (4*DMOD) + DMOD + h * DH + seg;
#pragma unroll
        for (int i = 0; i < 2; i++) {
            float4 q4 = *(const float4*)(qp + 4*i);
            float4 k4 = *(const float4*)(kp + 4*i);
            Qs[seg + 4*i + 0][r] = q4.x; Qs[seg + 4*i + 1][r] = q4.y;
            Qs[seg + 4*i + 2][r] = q4.z; Qs[seg + 4*i + 3][r] = q4.w;
            Ks[seg + 4*i + 0][r] = k4.x; Ks[seg + 4*i + 1][r] = k4.y;
            Ks[seg + 4*i + 2][r] = k4.z; Ks[seg + 4*i + 3][r] = k4.w;
        }
    }
    if (t < 192) { int r = t / 3, c = t % 3; xa[r][c] = xres[(n0 + r) * 3 + c]; }
    if (t >= 64 && t < 256) {
        int u = t - 64;
        if (u < 192) { int r = u / 3, c = u % 3; xb[r][c] = xres[(m0 + r) * 3 + c]; }
    }
    __syncthreads();

    int tm = t >> 4, tn = t & 15;
    float acc[4][4] = {};
#pragma unroll
    for (int k = 0; k < 32; k++) {
        float4 av = *(const float4*)&Qs[k][tm << 2];
        float4 bv = *(const float4*)&Ks[k][tn << 2];
        float a[4] = {av.x, av.y, av.z, av.w};
        float bb[4] = {bv.x, bv.y, bv.z, bv.w};
#pragma unroll
        for (int i = 0; i < 4; i++)
#pragma unroll
            for (int j = 0; j < 4; j++) acc[i][j] += a[i] * bb[j];
    }

    float inve = 1.f / c_eps[h];
    float wd = wdist[h] * 0.01f;
    const float scale = 0.17677669529663687f;
#pragma unroll
    for (int i = 0; i < 4; i++) {
        int nl = (tm << 2) + i;
        int n = n0 + nl;
        float ax0 = xa[nl][0], ax1 = xa[nl][1], ax2 = xa[nl][2];
        size_t base = ((size_t)h * NTOK + n) * NTOK + m0 + (tn << 2);
        float4 w4 = *(const float4*)(wrel + base);
        float e[4];
#pragma unroll
        for (int j = 0; j < 4; j++) {
            int ml = (tn << 2) + j;
            float dx = ax0 - xb[ml][0];
            float dy = ax1 - xb[ml][1];
            float dz = ax2 - xb[ml][2];
            float d2 = dx * dx + dy * dy + dz * dz;
            float wr = (j == 0) ? w4.x : (j == 1) ? w4.y : (j == 2) ? w4.z : w4.w;
            e[j] = __expf((acc[i][j] * scale + wr - wd * d2) * inve);
        }
        *(__nv_bfloat162*)(g_EK + base)     = __floats2bfloat162_rn(e[0], e[1]);
        *(__nv_bfloat162*)(g_EK + base + 2) = __floats2bfloat162_rn(e[2], e[3]);
    }
}

// ---------------- fused Sinkhorn iteration ----------------
// One kernel does the row pass AND accumulates column partials from registers,
// reading EK exactly once. Grid (NSTRIPE, NH), 256 threads (8 warps x 10 rows).
// Lane's fixed column set: col(c,j) = (c*32+lane)*8 + j, c=0..4, j=0..7.
__global__ void sink_fused(const float* __restrict__ mu) {
    __shared__ float evs[NTOK];
    __shared__ float colpart[8][NTOK];
    int h = blockIdx.y, stripe = blockIdx.x;
    int warp = threadIdx.x >> 5, lane = threadIdx.x & 31;
    for (int i = threadIdx.x; i < NTOK; i += 256) evs[i] = g_ev[h * NTOK + i];
    __syncthreads();

    float fi = 1.f / (1.f + c_eps[h]);
    float colacc[40];
#pragma unroll
    for (int k = 0; k < 40; k++) colacc[k] = 0.f;

    int rbase = stripe * ROWS_PER_STRIPE + warp * ROWS_PER_WARP;
    for (int r = 0; r < ROWS_PER_WARP; r++) {
        int n = rbase + r;
        const uint4* pv = (const uint4*)(g_EK + ((size_t)h * NTOK + n) * NTOK);
        float f[40];
        float acc = 0.f;
#pragma unroll
        for (int c = 0; c < 5; c++) {
            uint4 u = pv[c * 32 + lane];
            int jb = (c * 32 + lane) * 8;
            const __nv_bfloat162* hh = (const __nv_bfloat162*)&u;
            float2 f0 = __bfloat1622float2(hh[0]);
            float2 f1 = __bfloat1622float2(hh[1]);
            float2 f2 = __bfloat1622float2(hh[2]);
            float2 f3 = __bfloat1622float2(hh[3]);
            f[c*8+0] = f0.x; f[c*8+1] = f0.y; f[c*8+2] = f1.x; f[c*8+3] = f1.y;
            f[c*8+4] = f2.x; f[c*8+5] = f2.y; f[c*8+6] = f3.x; f[c*8+7] = f3.y;
            acc += f0.x * evs[jb + 0] + f0.y * evs[jb + 1]
                 + f1.x * evs[jb + 2] + f1.y * evs[jb + 3]
                 + f2.x * evs[jb + 4] + f2.y * evs[jb + 5]
                 + f3.x * evs[jb + 6] + f3.y * evs[jb + 7];
        }
#pragma unroll
        for (int o = 16; o; o >>= 1) acc += __shfl_xor_sync(0xffffffffu, acc, o);
        // every lane computes lu/eu (redundant but broadcast-free)
        float lu = fi * (logf(fmaxf(mu[h * NTOK + n], 1e-8f)) - logf(acc));
        float eu = __expf(lu);
        if (lane == 0) {
            g_lu[h * NTOK + n] = lu;
            g_eu[h * NTOK + n] = eu;
        }
#pragma unroll
        for (int k = 0; k < 40; k++) colacc[k] += f[k] * eu;
    }

    // per-warp partials -> smem (each warp writes its own row; no conflicts)
#pragma unroll
    for (int c = 0; c < 5; c++) {
        int jb = (c * 32 + lane) * 8;
#pragma unroll
        for (int j = 0; j < 8; j++) colpart[warp][jb + j] = colacc[c*8 + j];
    }
    __syncthreads();
    // block reduce 8 warps -> stripe partial
    for (int i = threadIdx.x; i < NTOK; i += 256) {
        float s = colpart[0][i];
#pragma unroll
        for (int w = 1; w < 8; w++) s += colpart[w][i];
        g_part[((size_t)h * NSTRIPE + stripe) * NTOK + i] = s;
    }
}

// finish: T_m = sum_stripes partial; lv = fi*(log(nu)-log(T)); ev = exp(lv)
__global__ void sink_colfin(const float* __restrict__ nu) {
    int i = blockIdx.x * 256 + threadIdx.x;
    if (i >= NH * NTOK) return;
    int h = i / NTOK, m = i % NTOK;
    const float* p = g_part + (size_t)h * NSTRIPE * NTOK + m;
    float T = 0.f;
#pragma unroll
    for (int s = 0; s < NSTRIPE; s++) T += p[(size_t)s * NTOK];
    float fi = 1.f / (1.f + c_eps[h]);
    float lv = fi * (logf(fmaxf(nu[i], 1e-8f)) - logf(T));
    g_lv[i] = lv;
    g_ev[i] = __expf(lv);
}

// ---------------- P application: P = eu*EK*ev ----------------
__global__ void papply_kernel(const float* __restrict__ xres) {
    int h = blockIdx.y;
    int warp = threadIdx.x >> 5, lane = threadIdx.x & 31;
    int row = blockIdx.x * 8 + warp;
    __shared__ float evs[NTOK];
    __shared__ float xs[3 * NTOK];
    __shared__ float vs[128 * 32];
    for (int i = threadIdx.x; i < NTOK; i += 256) evs[i] = g_ev[h * NTOK + i];
    for (int i = threadIdx.x; i < 3 * NTOK; i += 256) xs[i] = xres[i];
    float eu_r = g_eu[h * NTOK + row];
    float acc = 0.f, ax = 0.f, psum = 0.f;
    for (int mc = 0; mc < NTOK; mc += 128) {
        __syncthreads();
        for (int i = threadIdx.x; i < 128 * 32; i += 256) {
            int r = i >> 5, d = i & 31;
            vs[i] = g_qkvg[(size_t)(mc + r) * (4*DMOD) + 2*DMOD + h * DH + d];
        }
        __syncthreads();
        const __nv_bfloat16* lk = g_EK + ((size_t)h * NTOK + row) * NTOK + mc;
#pragma unroll
        for (int mj = 0; mj < 128; mj += 32) {
            float pl = eu_r * __bfloat162float(lk[mj + lane]) * evs[mc + mj + lane];
            psum += pl;
#pragma unroll
            for (int j = 0; j < 32; j++) {
                float p = __shfl_sync(0xffffffffu, pl, j);
                acc += p * vs[(mj + j) * 32 + lane];
                if (lane < 3) ax += p * xs[(mc + mj + j) * 3 + lane];
            }
        }
    }
    float ps = psum;
    for (int o = 16; o; o >>= 1) ps += __shfl_xor_sync(0xffffffffu, ps, o);
    float gt = g_qkvg[(size_t)row * (4*DMOD) + 3*DMOD + h * DH + lane];
    g_o[(size_t)row * DMOD + h * DH + lane] = acc / (1.f + __expf(-gt));
    if (lane < 3) g_xc[((size_t)h * NTOK + row) * 3 + lane] = ax;
    if (lane == 0) g_rows[h * NTOK + row] = ps;
}

__global__ void xout_kernel(const float* __restrict__ xres, const float* __restrict__ gamma,
                            float* __restrict__ out) {
    int n = blockIdx.x * 256 + threadIdx.x;
    if (n >= NTOK) return;
    float x0 = xres[n * 3 + 0], x1 = xres[n * 3 + 1], x2 = xres[n * 3 + 2];
    float a0 = 0.f, a1 = 0.f, a2 = 0.f;
    for (int h = 0; h < NH; h++) {
        float r = 1.f / (g_rows[h * NTOK + n] + 1e-8f);
        float gm = gamma[h];
        a0 += gm * (x0 - g_xc[((size_t)h * NTOK + n) * 3 + 0] * r);
        a1 += gm * (x1 - g_xc[((size_t)h * NTOK + n) * 3 + 1] * r);
        a2 += gm * (x2 - g_xc[((size_t)h * NTOK + n) * 3 + 2] * r);
    }
    out[n * 3 + 0] = x0 + a0;
    out[n * 3 + 1] = x1 + a1;
    out[n * 3 + 2] = x2 + a2;
}

__global__ void silumul_kernel() {
    int i = blockIdx.x * 256 + threadIdx.x;
    if (i < NTOK * DFF) {
        int n = i >> 11, j = i & (DFF - 1);
        float a = g_t12[(size_t)n * (2*DFF) + j];
        float b = g_t12[(size_t)n * (2*DFF) + DFF + j];
        g_t1[i] = a / (1.f + __expf(-a)) * b;
    }
}

// ---------------- launch ----------------
extern "C" void kernel_launch(void* const* d_in, const int* in_sizes, int n_in,
                              void* d_out, int out_size) {
    const float* h_in  = (const float*)d_in[0];
    const float* x_res = (const float*)d_in[1];
    const float* mu    = (const float*)d_in[2];
    const float* nu    = (const float*)d_in[3];
    const float* wrel  = (const float*)d_in[4];
    const float* wdist = (const float*)d_in[5];
    const float* ln_ag = (const float*)d_in[7];
    const float* ln_ab = (const float*)d_in[8];
    const float* Wq    = (const float*)d_in[9];
    const float* Wk    = (const float*)d_in[10];
    const float* Wv    = (const float*)d_in[11];
    const float* Wg    = (const float*)d_in[12];
    const float* Wo    = (const float*)d_in[13];
    const float* gamma = (const float*)d_in[14];
    const float* ln_fg = (const float*)d_in[15];
    const float* ln_fb = (const float*)d_in[16];
    const float* W1    = (const float*)d_in[17];
    const float* W2    = (const float*)d_in[18];
    const float* W3    = (const float*)d_in[19];
    float* out = (float*)d_out;

    float *p_hn, *p_qkvg, *p_lu, *p_lv, *p_ev, *p_o, *p_h2, *p_hf, *p_t1, *p_part, *p_t12;
    cudaGetSymbolAddress((void**)&p_hn,     g_hn);
    cudaGetSymbolAddress((void**)&p_qkvg,   g_qkvg);
    cudaGetSymbolAddress((void**)&p_lu,     g_lu);
    cudaGetSymbolAddress((void**)&p_lv,     g_lv);
    cudaGetSymbolAddress((void**)&p_ev,     g_ev);
    cudaGetSymbolAddress((void**)&p_o,      g_o);
    cudaGetSymbolAddress((void**)&p_h2,     g_h2);
    cudaGetSymbolAddress((void**)&p_hf,     g_hf);
    cudaGetSymbolAddress((void**)&p_t1,     g_t1);
    cudaGetSymbolAddress((void**)&p_part,   g_part);
    cudaGetSymbolAddress((void**)&p_t12,    g_t12);

    const int OUT_X  = NTOK * DMOD;
    const int OUT_LU = OUT_X + NTOK * 3;
    const int OUT_LV = OUT_LU + NH * NTOK;

    ones_kernel<<<(NH * NTOK + 1023) / 1024, 1024>>>(p_ev, NH * NTOK);  // ev = exp(0)
    ln_kernel<<<NTOK, 256>>>(h_in, ln_ag, ln_ab, p_hn);

    Ptr4 bqkvg; bqkvg.p[0] = Wq; bqkvg.p[1] = Wk; bqkvg.p[2] = Wv; bqkvg.p[3] = Wg;
    tc_gemm<<<dim3(4*DMOD/64, NTOK/128, 1), 256>>>(p_hn, bqkvg, p_qkvg, 4*DMOD, DMOD, DMOD, DMOD);

    qkln_kernel<<<dim3((NTOK * NH) / 8, 2), 256>>>(p_qkvg);

    build_logk<<<dim3(NTOK / 64, NTOK / 64, NH), 256>>>(wrel, x_res, wdist);

    dim3 gfuse(NSTRIPE, NH);
    for (int it = 0; it < NITER; it++) {
        sink_fused<<<gfuse, 256>>>(mu);
        sink_colfin<<<(NH * NTOK + 255) / 256, 256>>>(nu);
    }

    dim3 grow(NTOK / 8, NH);
    papply_kernel<<<grow, 256>>>(x_res);

    Ptr4 bWo; bWo.p[0] = Wo; bWo.p[1] = Wo; bWo.p[2] = Wo; bWo.p[3] = Wo;
    tc_gemm<<<dim3(DMOD/64, NTOK/128, 2), 256>>>(p_o, bWo, p_part, DMOD, DMOD, DMOD, DMOD/2);
    reduce_add<<<(NTOK*DMOD)/256, 256>>>(h_in, p_part, 2, p_h2, NTOK*DMOD);

    xout_kernel<<<(NTOK + 255) / 256, 256>>>(x_res, gamma, out + OUT_X);

    ln_kernel<<<NTOK, 256>>>(p_h2, ln_fg, ln_fb, p_hf);
    Ptr4 b12; b12.p[0] = W1; b12.p[1] = W2; b12.p[2] = W1; b12.p[3] = W1;
    tc_gemm<<<dim3(2*DFF/64, NTOK/128, 1), 256>>>(p_hf, b12, p_t12, 2*DFF, DMOD, DFF, DMOD);
    silumul_kernel<<<(NTOK * DFF) / 256, 256>>>();
    Ptr4 bW3; bW3.p[0] = W3; bW3.p[1] = W3; bW3.p[2] = W3; bW3.p[3] = W3;
    tc_gemm<<<dim3(DMOD/64, NTOK/128, 4), 256>>>(p_t1, bW3, p_part, DMOD, DFF, DMOD, DFF/4);
    reduce_add<<<(NTOK*DMOD)/256, 256>>>(p_h2, p_part, 4, out, NTOK*DMOD);

    copy_uv_kernel<<<(NH * NTOK + 1023) / 1024, 1024>>>(p_lu, p_lv, out + OUT_LU, out + OUT_LV);
}

// round 10
// speedup vs baseline: 1.8105x; 1.4061x over previous
#include <cuda_runtime.h>
#include <cuda_fp16.h>
#include <cuda_bf16.h>
#include <math.h>

#define NTOK 1280
#define DMOD 512
#define NH   16
#define DH   32
#define DFF  2048
#define NITER 20
#define NSTRIPE 16
#define ROWS_PER_STRIPE 80   // 16*80 = 1280
#define ROWS_PER_WARP 10     // 8 warps * 10 = 80
#define WCOLS 40             // W: 32 V + 3 x + 1 ones + 4 pad

// ---------------- scratch ----------------
__device__ __nv_bfloat16 g_EK[NH*NTOK*NTOK];  // exp(logK), bf16
__device__ __nv_bfloat16 g_Wt[NH*WCOLS*NTOK]; // W^T per head: [d][m], m contiguous
__device__ float g_hn  [NTOK*DMOD];
__device__ float g_qkvg[NTOK*4*DMOD];         // [q | k | v | gate]
__device__ float g_lu [NH*NTOK];
__device__ float g_lv [NH*NTOK];
__device__ float g_eu [NH*NTOK];              // exp(lu)
__device__ float g_ev [NH*NTOK];              // exp(lv)
__device__ float g_xc [NH*NTOK*3];
__device__ float g_rows[NH*NTOK];
__device__ float g_o  [NTOK*DMOD];
__device__ float g_h2 [NTOK*DMOD];
__device__ float g_hf [NTOK*DMOD];
__device__ float g_t12[NTOK*2*DFF];           // [t1 | t2]
__device__ float g_t1 [NTOK*DFF];
__device__ float g_part[4*NTOK*DMOD];         // split-K partials / sinkhorn col partials

__constant__ float c_eps[NH] = {0.5f,0.5f,0.5f,0.5f, 1.f,1.f,1.f,1.f,
                                2.f,2.f,2.f,2.f, 4.f,4.f,4.f,4.f};

struct Ptr4 { const float* p[4]; };

// ---------------- utility kernels ----------------
__global__ void copy_uv_kernel(const float* __restrict__ lu, const float* __restrict__ lv,
                               float* __restrict__ o1, float* __restrict__ o2) {
    int i = blockIdx.x * blockDim.x + threadIdx.x;
    if (i < NH*NTOK) { o1[i] = lu[i]; o2[i] = lv[i]; }
}

__global__ void ln_kernel(const float* __restrict__ in, const float* __restrict__ g,
                          const float* __restrict__ b, float* __restrict__ out) {
    int row = blockIdx.x;
    int t = threadIdx.x;
    const float* x = in + (size_t)row * DMOD;
    float v0 = x[t], v1 = x[t + 256];
    __shared__ float red[256];
    red[t] = v0 + v1;
    __syncthreads();
    for (int o = 128; o > 0; o >>= 1) { if (t < o) red[t] += red[t + o]; __syncthreads(); }
    float mean = red[0] * (1.f / DMOD);
    __syncthreads();
    float d0 = v0 - mean, d1 = v1 - mean;
    red[t] = d0 * d0 + d1 * d1;
    __syncthreads();
    for (int o = 128; o > 0; o >>= 1) { if (t < o) red[t] += red[t + o]; __syncthreads(); }
    float r = rsqrtf(red[0] * (1.f / DMOD) + 1e-5f);
    out[(size_t)row * DMOD + t]       = d0 * r * g[t]       + b[t];
    out[(size_t)row * DMOD + t + 256] = d1 * r * g[t + 256] + b[t + 256];
}

__global__ void qkln_kernel(float* __restrict__ base) {
    int gidx = blockIdx.x * 8 + (threadIdx.x >> 5);
    int lane = threadIdx.x & 31;
    if (gidx >= NTOK * NH) return;
    int n = gidx / NH, h = gidx % NH;
    float* p = base + (size_t)n * (4*DMOD) + blockIdx.y * DMOD + h * DH;
    float v = p[lane];
    float s = v;
    for (int o = 16; o; o >>= 1) s += __shfl_xor_sync(0xffffffffu, s, o);
    float mean = s * (1.f / 32.f);
    float d = v - mean;
    float s2 = d * d;
    for (int o = 16; o; o >>= 1) s2 += __shfl_xor_sync(0xffffffffu, s2, o);
    p[lane] = d * rsqrtf(s2 * (1.f / 32.f) + 1e-5f);
}

// ---------------- TF32 tensor-core GEMM ----------------
__device__ __forceinline__ unsigned f2tf32(float f) {
    unsigned u;
    asm("cvt.rna.tf32.f32 %0, %1;" : "=r"(u) : "f"(f));
    return u;
}

__device__ __forceinline__ void mma_tf32(float c[4], const unsigned a[4], const unsigned b[2]) {
    asm volatile("mma.sync.aligned.m16n8k8.row.col.f32.tf32.tf32.f32 "
        "{%0,%1,%2,%3}, {%4,%5,%6,%7}, {%8,%9}, {%0,%1,%2,%3};"
        : "+f"(c[0]), "+f"(c[1]), "+f"(c[2]), "+f"(c[3])
        : "r"(a[0]), "r"(a[1]), "r"(a[2]), "r"(a[3]), "r"(b[0]), "r"(b[1]));
}

__device__ __forceinline__ void mma_bf16(float c[4], const unsigned a[4], const unsigned b[2]) {
    asm volatile("mma.sync.aligned.m16n8k16.row.col.f32.bf16.bf16.f32 "
        "{%0,%1,%2,%3}, {%4,%5,%6,%7}, {%8,%9}, {%0,%1,%2,%3};"
        : "+f"(c[0]), "+f"(c[1]), "+f"(c[2]), "+f"(c[3])
        : "r"(a[0]), "r"(a[1]), "r"(a[2]), "r"(a[3]), "r"(b[0]), "r"(b[1]));
}

__global__ void tc_gemm(const float* __restrict__ A, Ptr4 B4, float* __restrict__ C,
                        int Nn, int K, int colsPer, int KC) {
    __shared__ float As[32][136];
    __shared__ float Bs[32][72];
    int tid = threadIdx.x;
    int m0 = blockIdx.y * 128, n0 = blockIdx.x * 64;
    const float* B = B4.p[n0 / colsPer] + (size_t)(n0 % colsPer) * K;
    int kbeg = blockIdx.z * KC, kend = kbeg + KC;

    int arow = tid >> 1, akseg = (tid & 1) << 4;
    int brow = tid & 63, bkseg = (tid >> 6) << 3;
    const float* Ap = A + (size_t)(m0 + arow) * K + akseg;
    const float* Bp = B + (size_t)brow * K + bkseg;

    int lane = tid & 31, g = lane >> 2, t = lane & 3;
    int wm = tid >> 6;
    int wn = (tid >> 5) & 1;
    int mBase = wm * 32, nBase = wn * 32;

    float c[2][4][4];
#pragma unroll
    for (int mi = 0; mi < 2; mi++)
#pragma unroll
        for (int ni = 0; ni < 4; ni++)
#pragma unroll
            for (int r = 0; r < 4; r++) c[mi][ni][r] = 0.f;

    for (int k0 = kbeg; k0 < kend; k0 += 32) {
        __syncthreads();
#pragma unroll
        for (int i = 0; i < 4; i++) {
            float4 a4 = *(const float4*)(Ap + k0 + 4 * i);
            As[akseg + 4*i + 0][arow] = __uint_as_float(f2tf32(a4.x));
            As[akseg + 4*i + 1][arow] = __uint_as_float(f2tf32(a4.y));
            As[akseg + 4*i + 2][arow] = __uint_as_float(f2tf32(a4.z));
            As[akseg + 4*i + 3][arow] = __uint_as_float(f2tf32(a4.w));
        }
#pragma unroll
        for (int i = 0; i < 2; i++) {
            float4 b4 = *(const float4*)(Bp + k0 + 4 * i);
            Bs[bkseg + 4*i + 0][brow] = __uint_as_float(f2tf32(b4.x));
            Bs[bkseg + 4*i + 1][brow] = __uint_as_float(f2tf32(b4.y));
            Bs[bkseg + 4*i + 2][brow] = __uint_as_float(f2tf32(b4.z));
            Bs[bkseg + 4*i + 3][brow] = __uint_as_float(f2tf32(b4.w));
        }
        __syncthreads();
#pragma unroll
        for (int ks = 0; ks < 32; ks += 8) {
            unsigned a[2][4], b[4][2];
#pragma unroll
            for (int mi = 0; mi < 2; mi++) {
                int mo = mBase + mi * 16 + g;
                a[mi][0] = __float_as_uint(As[ks + t][mo]);
                a[mi][1] = __float_as_uint(As[ks + t][mo + 8]);
                a[mi][2] = __float_as_uint(As[ks + t + 4][mo]);
                a[mi][3] = __float_as_uint(As[ks + t + 4][mo + 8]);
            }
#pragma unroll
            for (int ni = 0; ni < 4; ni++) {
                int no = nBase + ni * 8 + g;
                b[ni][0] = __float_as_uint(Bs[ks + t][no]);
                b[ni][1] = __float_as_uint(Bs[ks + t + 4][no]);
            }
#pragma unroll
            for (int mi = 0; mi < 2; mi++)
#pragma unroll
                for (int ni = 0; ni < 4; ni++)
                    mma_tf32(c[mi][ni], a[mi], b[ni]);
        }
    }

    float* Co = C + (size_t)blockIdx.z * NTOK * Nn;
#pragma unroll
    for (int mi = 0; mi < 2; mi++) {
        int r0 = m0 + mBase + mi * 16 + g;
#pragma unroll
        for (int ni = 0; ni < 4; ni++) {
            int col = n0 + nBase + ni * 8 + 2 * t;
            *(float2*)(Co + (size_t)r0 * Nn + col)       = make_float2(c[mi][ni][0], c[mi][ni][1]);
            *(float2*)(Co + (size_t)(r0 + 8) * Nn + col) = make_float2(c[mi][ni][2], c[mi][ni][3]);
        }
    }
}

__global__ void reduce_add(const float* __restrict__ R, const float* __restrict__ part,
                           int Z, float* __restrict__ out, int n) {
    int i = blockIdx.x * 256 + threadIdx.x;
    if (i >= n) return;
    float a = R[i];
    for (int z = 0; z < Z; z++) a += part[(size_t)z * n + i];
    out[i] = a;
}

// ---------------- build EK = exp(logK) in bf16 ----------------
__global__ void build_logk(const float* __restrict__ wrel, const float* __restrict__ xres,
                           const float* __restrict__ wdist) {
    __shared__ float Qs[32][68];
    __shared__ float Ks[32][68];
    __shared__ float xa[64][3], xb[64][3];
    int h = blockIdx.z;
    int n0 = blockIdx.y * 64, m0 = blockIdx.x * 64;
    int t = threadIdx.x;

    {
        int r = t >> 2, seg = (t & 3) << 3;
        const float* qp = g_qkvg + (size_t)(n0 + r) * (4*DMOD) + h * DH + seg;
        const float* kp = g_qkvg + (size_t)(m0 + r) * (4*DMOD) + DMOD + h * DH + seg;
#pragma unroll
        for (int i = 0; i < 2; i++) {
            float4 q4 = *(const float4*)(qp + 4*i);
            float4 k4 = *(const float4*)(kp + 4*i);
            Qs[seg + 4*i + 0][r] = q4.x; Qs[seg + 4*i + 1][r] = q4.y;
            Qs[seg + 4*i + 2][r] = q4.z; Qs[seg + 4*i + 3][r] = q4.w;
            Ks[seg + 4*i + 0][r] = k4.x; Ks[seg + 4*i + 1][r] = k4.y;
            Ks[seg + 4*i + 2][r] = k4.z; Ks[seg + 4*i + 3][r] = k4.w;
        }
    }
    if (t < 192) { int r = t / 3, c = t % 3; xa[r][c] = xres[(n0 + r) * 3 + c]; }
    if (t >= 64 && t < 256) {
        int u = t - 64;
        if (u < 192) { int r = u / 3, c = u % 3; xb[r][c] = xres[(m0 + r) * 3 + c]; }
    }
    __syncthreads();

    int tm = t >> 4, tn = t & 15;
    float acc[4][4] = {};
#pragma unroll
    for (int k = 0; k < 32; k++) {
        float4 av = *(const float4*)&Qs[k][tm << 2];
        float4 bv = *(const float4*)&Ks[k][tn << 2];
        float a[4] = {av.x, av.y, av.z, av.w};
        float bb[4] = {bv.x, bv.y, bv.z, bv.w};
#pragma unroll
        for (int i = 0; i < 4; i++)
#pragma unroll
            for (int j = 0; j < 4; j++) acc[i][j] += a[i] * bb[j];
    }

    float inve = 1.f / c_eps[h];
    float wd = wdist[h] * 0.01f;
    const float scale = 0.17677669529663687f;
#pragma unroll
    for (int i = 0; i < 4; i++) {
        int nl = (tm << 2) + i;
        int n = n0 + nl;
        float ax0 = xa[nl][0], ax1 = xa[nl][1], ax2 = xa[nl][2];
        size_t base = ((size_t)h * NTOK + n) * NTOK + m0 + (tn << 2);
        float4 w4 = *(const float4*)(wrel + base);
        float e[4];
#pragma unroll
        for (int j = 0; j < 4; j++) {
            int ml = (tn << 2) + j;
            float dx = ax0 - xb[ml][0];
            float dy = ax1 - xb[ml][1];
            float dz = ax2 - xb[ml][2];
            float d2 = dx * dx + dy * dy + dz * dz;
            float wr = (j == 0) ? w4.x : (j == 1) ? w4.y : (j == 2) ? w4.z : w4.w;
            e[j] = __expf((acc[i][j] * scale + wr - wd * d2) * inve);
        }
        *(__nv_bfloat162*)(g_EK + base)     = __floats2bfloat162_rn(e[0], e[1]);
        *(__nv_bfloat162*)(g_EK + base + 2) = __floats2bfloat162_rn(e[2], e[3]);
    }
}

// ---------------- fused Sinkhorn iteration ----------------
// Prologue: reconstruct ev from previous iteration's column partials (it>0) or 1 (it==0).
// Body: row GEMV + register column accumulation, EK read exactly once.
__global__ void sink_fused(const float* __restrict__ mu, const float* __restrict__ nu, int it) {
    __shared__ float evs[NTOK];
    __shared__ float colpart[8][NTOK];
    int h = blockIdx.y, stripe = blockIdx.x;
    int warp = threadIdx.x >> 5, lane = threadIdx.x & 31;
    float fi = 1.f / (1.f + c_eps[h]);

    if (it == 0) {
        for (int i = threadIdx.x; i < NTOK; i += 256) evs[i] = 1.f;
    } else {
        for (int i = threadIdx.x; i < NTOK; i += 256) {
            const float* p = g_part + (size_t)h * NSTRIPE * NTOK + i;
            float T = 0.f;
#pragma unroll
            for (int s = 0; s < NSTRIPE; s++) T += p[(size_t)s * NTOK];
            evs[i] = __expf(fi * (__logf(fmaxf(nu[h * NTOK + i], 1e-8f)) - __logf(T)));
        }
    }
    __syncthreads();

    float colacc[40];
#pragma unroll
    for (int k = 0; k < 40; k++) colacc[k] = 0.f;

    int rbase = stripe * ROWS_PER_STRIPE + warp * ROWS_PER_WARP;
    for (int r = 0; r < ROWS_PER_WARP; r++) {
        int n = rbase + r;
        const uint4* pv = (const uint4*)(g_EK + ((size_t)h * NTOK + n) * NTOK);
        float f[40];
        float acc = 0.f;
#pragma unroll
        for (int c = 0; c < 5; c++) {
            uint4 u = pv[c * 32 + lane];
            int jb = (c * 32 + lane) * 8;
            const __nv_bfloat162* hh = (const __nv_bfloat162*)&u;
            float2 f0 = __bfloat1622float2(hh[0]);
            float2 f1 = __bfloat1622float2(hh[1]);
            float2 f2 = __bfloat1622float2(hh[2]);
            float2 f3 = __bfloat1622float2(hh[3]);
            f[c*8+0] = f0.x; f[c*8+1] = f0.y; f[c*8+2] = f1.x; f[c*8+3] = f1.y;
            f[c*8+4] = f2.x; f[c*8+5] = f2.y; f[c*8+6] = f3.x; f[c*8+7] = f3.y;
            acc += f0.x * evs[jb + 0] + f0.y * evs[jb + 1]
                 + f1.x * evs[jb + 2] + f1.y * evs[jb + 3]
                 + f2.x * evs[jb + 4] + f2.y * evs[jb + 5]
                 + f3.x * evs[jb + 6] + f3.y * evs[jb + 7];
        }
#pragma unroll
        for (int o = 16; o; o >>= 1) acc += __shfl_xor_sync(0xffffffffu, acc, o);
        float lu = fi * (__logf(fmaxf(mu[h * NTOK + n], 1e-8f)) - __logf(acc));
        float eu = __expf(lu);
        if (lane == 0) {
            g_lu[h * NTOK + n] = lu;
            g_eu[h * NTOK + n] = eu;
        }
#pragma unroll
        for (int k = 0; k < 40; k++) colacc[k] += f[k] * eu;
    }

#pragma unroll
    for (int c = 0; c < 5; c++) {
        int jb = (c * 32 + lane) * 8;
#pragma unroll
        for (int j = 0; j < 8; j++) colpart[warp][jb + j] = colacc[c*8 + j];
    }
    __syncthreads();
    for (int i = threadIdx.x; i < NTOK; i += 256) {
        float s = colpart[0][i];
#pragma unroll
        for (int w = 1; w < 8; w++) s += colpart[w][i];
        g_part[((size_t)h * NSTRIPE + stripe) * NTOK + i] = s;
    }
}

// final column finish (outputs lv and ev)
__global__ void sink_colfin(const float* __restrict__ nu) {
    int i = blockIdx.x * 256 + threadIdx.x;
    if (i >= NH * NTOK) return;
    int h = i / NTOK;
    int m = i % NTOK;
    const float* p = g_part + (size_t)h * NSTRIPE * NTOK + m;
    float T = 0.f;
#pragma unroll
    for (int s = 0; s < NSTRIPE; s++) T += p[(size_t)s * NTOK];
    float fi = 1.f / (1.f + c_eps[h]);
    float lv = fi * (logf(fmaxf(nu[i], 1e-8f)) - logf(T));
    g_lv[i] = lv;
    g_ev[i] = __expf(lv);
}

// ---------------- build W^T = (diag(ev)[V | x | 1])^T in bf16 ----------------
// grid (NTOK/256, NH); Wt[h][d][m], d: 0-31 V, 32-34 x, 35 ones, 36-39 zero
__global__ void build_W(const float* __restrict__ xres) {
    __shared__ float Vs[256][33];
    __shared__ float evs[256];
    __shared__ float xs[256][3];
    int h = blockIdx.y;
    int m0 = blockIdx.x * 256;
    int tid = threadIdx.x;
    for (int i = tid; i < 256 * 32; i += 256) {
        int r = i >> 5, c = i & 31;
        Vs[r][c] = g_qkvg[(size_t)(m0 + r) * (4*DMOD) + 2*DMOD + h * DH + c];
    }
    evs[tid] = g_ev[h * NTOK + m0 + tid];
    xs[tid][0] = xres[(m0 + tid) * 3 + 0];
    xs[tid][1] = xres[(m0 + tid) * 3 + 1];
    xs[tid][2] = xres[(m0 + tid) * 3 + 2];
    __syncthreads();
    float e = evs[tid];
#pragma unroll
    for (int d = 0; d < WCOLS; d++) {
        float v;
        if (d < 32) v = e * Vs[tid][d];
        else if (d < 35) v = e * xs[tid][d - 32];
        else if (d == 35) v = e;
        else v = 0.f;
        g_Wt[((size_t)h * WCOLS + d) * NTOK + m0 + tid] = __float2bfloat16(v);
    }
}

// ---------------- papply via bf16 MMA: C = EK @ W, then scale by eu ----------------
// grid (NTOK/128, NH), 256 threads (8 warps, warp w owns rows w*16..w*16+15)
__global__ void papply_mma(const float* __restrict__ xres) {
    __shared__ unsigned As_u[128 * 20];   // 128 rows x 32 k bf16, stride 20 words
    __shared__ unsigned Bs_u[WCOLS * 20]; // 40 d x 32 k bf16, stride 20 words
    __shared__ float Cs[128 * 41];
    __shared__ float eus[128];
    int h = blockIdx.y;
    int n0 = blockIdx.x * 128;
    int tid = threadIdx.x;
    int warp = tid >> 5, lane = tid & 31;
    int g = lane >> 2, t = lane & 3;

    if (tid < 128) eus[tid] = g_eu[h * NTOK + n0 + tid];

    float c[5][4];
#pragma unroll
    for (int nt = 0; nt < 5; nt++)
#pragma unroll
        for (int r = 0; r < 4; r++) c[nt][r] = 0.f;

    int arow = tid >> 1, aq = (tid & 1) * 2;
    for (int k0 = 0; k0 < NTOK; k0 += 32) {
        __syncthreads();
        // A tile: EK[n0+row][k0..k0+31]
        {
            const uint4* src = (const uint4*)(g_EK + ((size_t)h * NTOK + n0 + arow) * NTOK + k0);
#pragma unroll
            for (int j = 0; j < 2; j++) {
                *(uint4*)(As_u + arow * 20 + (aq + j) * 4) = src[aq + j];
            }
        }
        // B tile: Wt[d][k0..k0+31]
        if (tid < 160) {
            int d = tid >> 2, q = tid & 3;
            const uint4* src = (const uint4*)(g_Wt + ((size_t)h * WCOLS + d) * NTOK + k0);
            *(uint4*)(Bs_u + d * 20 + q * 4) = src[q];
        }
        __syncthreads();
#pragma unroll
        for (int ks2 = 0; ks2 < 16; ks2 += 8) {
            const unsigned* au = As_u + (warp * 16 + g) * 20;
            const unsigned* au8 = au + 8 * 20;
            unsigned a[4];
            a[0] = au[ks2 + t];
            a[1] = au8[ks2 + t];
            a[2] = au[ks2 + t + 4];
            a[3] = au8[ks2 + t + 4];
#pragma unroll
            for (int nt = 0; nt < 5; nt++) {
                const unsigned* bu = Bs_u + (nt * 8 + g) * 20;
                unsigned b[2];
                b[0] = bu[ks2 + t];
                b[1] = bu[ks2 + t + 4];
                mma_bf16(c[nt], a, b);
            }
        }
    }

    // write fragments to Cs
#pragma unroll
    for (int nt = 0; nt < 5; nt++) {
        int row = warp * 16 + g;
        int col = nt * 8 + 2 * t;
        Cs[row * 41 + col]     = c[nt][0];
        Cs[row * 41 + col + 1] = c[nt][1];
        Cs[(row + 8) * 41 + col]     = c[nt][2];
        Cs[(row + 8) * 41 + col + 1] = c[nt][3];
    }
    __syncthreads();

    // epilogue
    for (int i = tid; i < 128 * 32; i += 256) {
        int r = i >> 5, d = i & 31;
        int n = n0 + r;
        float attn = eus[r] * Cs[r * 41 + d];
        float gt = g_qkvg[(size_t)n * (4*DMOD) + 3*DMOD + h * DH + d];
        g_o[(size_t)n * DMOD + h * DH + d] = attn / (1.f + __expf(-gt));
    }
    for (int r = tid; r < 128; r += 256) {
        int n = n0 + r;
        float e = eus[r];
        g_xc[((size_t)h * NTOK + n) * 3 + 0] = e * Cs[r * 41 + 32];
        g_xc[((size_t)h * NTOK + n) * 3 + 1] = e * Cs[r * 41 + 33];
        g_xc[((size_t)h * NTOK + n) * 3 + 2] = e * Cs[r * 41 + 34];
        g_rows[h * NTOK + n] = e * Cs[r * 41 + 35];
    }
}

__global__ void xout_kernel(const float* __restrict__ xres, const float* __restrict__ gamma,
                            float* __restrict__ out) {
    int n = blockIdx.x * 256 + threadIdx.x;
    if (n >= NTOK) return;
    float x0 = xres[n * 3 + 0], x1 = xres[n * 3 + 1], x2 = xres[n * 3 + 2];
    float a0 = 0.f, a1 = 0.f, a2 = 0.f;
    for (int h = 0; h < NH; h++) {
        float r = 1.f / (g_rows[h * NTOK + n] + 1e-8f);
        float gm = gamma[h];
        a0 += gm * (x0 - g_xc[((size_t)h * NTOK + n) * 3 + 0] * r);
        a1 += gm * (x1 - g_xc[((size_t)h * NTOK + n) * 3 + 1] * r);
        a2 += gm * (x2 - g_xc[((size_t)h * NTOK + n) * 3 + 2] * r);
    }
    out[n * 3 + 0] = x0 + a0;
    out[n * 3 + 1] = x1 + a1;
    out[n * 3 + 2] = x2 + a2;
}

__global__ void silumul_kernel() {
    int i = blockIdx.x * 256 + threadIdx.x;
    if (i < NTOK * DFF) {
        int n = i >> 11, j = i & (DFF - 1);
        float a = g_t12[(size_t)n * (2*DFF) + j];
        float b = g_t12[(size_t)n * (2*DFF) + DFF + j];
        g_t1[i] = a / (1.f + __expf(-a)) * b;
    }
}

// ---------------- launch ----------------
extern "C" void kernel_launch(void* const* d_in, const int* in_sizes, int n_in,
                              void* d_out, int out_size) {
    const float* h_in  = (const float*)d_in[0];
    const float* x_res = (const float*)d_in[1];
    const float* mu    = (const float*)d_in[2];
    const float* nu    = (const float*)d_in[3];
    const float* wrel  = (const float*)d_in[4];
    const float* wdist = (const float*)d_in[5];
    const float* ln_ag = (const float*)d_in[7];
    const float* ln_ab = (const float*)d_in[8];
    const float* Wq    = (const float*)d_in[9];
    const float* Wk    = (const float*)d_in[10];
    const float* Wv    = (const float*)d_in[11];
    const float* Wg    = (const float*)d_in[12];
    const float* Wo    = (const float*)d_in[13];
    const float* gamma = (const float*)d_in[14];
    const float* ln_fg = (const float*)d_in[15];
    const float* ln_fb = (const float*)d_in[16];
    const float* W1    = (const float*)d_in[17];
    const float* W2    = (const float*)d_in[18];
    const float* W3    = (const float*)d_in[19];
    float* out = (float*)d_out;

    float *p_hn, *p_qkvg, *p_lu, *p_lv, *p_o, *p_h2, *p_hf, *p_t1, *p_part, *p_t12;
    cudaGetSymbolAddress((void**)&p_hn,     g_hn);
    cudaGetSymbolAddress((void**)&p_qkvg,   g_qkvg);
    cudaGetSymbolAddress((void**)&p_lu,     g_lu);
    cudaGetSymbolAddress((void**)&p_lv,     g_lv);
    cudaGetSymbolAddress((void**)&p_o,      g_o);
    cudaGetSymbolAddress((void**)&p_h2,     g_h2);
    cudaGetSymbolAddress((void**)&p_hf,     g_hf);
    cudaGetSymbolAddress((void**)&p_t1,     g_t1);
    cudaGetSymbolAddress((void**)&p_part,   g_part);
    cudaGetSymbolAddress((void**)&p_t12,    g_t12);

    const int OUT_X  = NTOK * DMOD;
    const int OUT_LU = OUT_X + NTOK * 3;
    const int OUT_LV = OUT_LU + NH * NTOK;

    ln_kernel<<<NTOK, 256>>>(h_in, ln_ag, ln_ab, p_hn);

    Ptr4 bqkvg; bqkvg.p[0] = Wq; bqkvg.p[1] = Wk; bqkvg.p[2] = Wv; bqkvg.p[3] = Wg;
    tc_gemm<<<dim3(4*DMOD/64, NTOK/128, 1), 256>>>(p_hn, bqkvg, p_qkvg, 4*DMOD, DMOD, DMOD, DMOD);

    qkln_kernel<<<dim3((NTOK * NH) / 8, 2), 256>>>(p_qkvg);

    build_logk<<<dim3(NTOK / 64, NTOK / 64, NH), 256>>>(wrel, x_res, wdist);

    dim3 gfuse(NSTRIPE, NH);
    for (int it = 0; it < NITER; it++)
        sink_fused<<<gfuse, 256>>>(mu, nu, it);
    sink_colfin<<<(NH * NTOK + 255) / 256, 256>>>(nu);

    build_W<<<dim3(NTOK / 256, NH), 256>>>(x_res);
    papply_mma<<<dim3(NTOK / 128, NH), 256>>>(x_res);

    Ptr4 bWo; bWo.p[0] = Wo; bWo.p[1] = Wo; bWo.p[2] = Wo; bWo.p[3] = Wo;
    tc_gemm<<<dim3(DMOD/64, NTOK/128, 2), 256>>>(p_o, bWo, p_part, DMOD, DMOD, DMOD, DMOD/2);
    reduce_add<<<(NTOK*DMOD)/256, 256>>>(h_in, p_part, 2, p_h2, NTOK*DMOD);

    xout_kernel<<<(NTOK + 255) / 256, 256>>>(x_res, gamma, out + OUT_X);

    ln_kernel<<<NTOK, 256>>>(p_h2, ln_fg, ln_fb, p_hf);
    Ptr4 b12; b12.p[0] = W1; b12.p[1] = W2; b12.p[2] = W1; b12.p[3] = W1;
    tc_gemm<<<dim3(2*DFF/64, NTOK/128, 1), 256>>>(p_hf, b12, p_t12, 2*DFF, DMOD, DFF, DMOD);
    silumul_kernel<<<(NTOK * DFF) / 256, 256>>>();
    Ptr4 bW3; bW3.p[0] = W3; bW3.p[1] = W3; bW3.p[2] = W3; bW3.p[3] = W3;
    tc_gemm<<<dim3(DMOD/64, NTOK/128, 4), 256>>>(p_t1, bW3, p_part, DMOD, DFF, DMOD, DFF/4);
    reduce_add<<<(NTOK*DMOD)/256, 256>>>(p_h2, p_part, 4, out, NTOK*DMOD);

    copy_uv_kernel<<<(NH * NTOK + 1023) / 1024, 1024>>>(p_lu, p_lv, out + OUT_LU, out + OUT_LV);
}